// round 1
// baseline (speedup 1.0000x reference)
#include <cuda_runtime.h>

// Problem constants (from reference setup_inputs)
constexpr int Bb = 108;
constexpr int Nn = 392;
constexpr int Ii = 256;
constexpr int Hh = 4;
constexpr int Oo = 64;
constexpr int HO = 256;         // H*O
constexpr int BN = Bb * Nn;     // 42336

#define ALPHA_C   0.2f
#define LEAKY_C   0.2f
#define NEG_INF_C (-1.0e9f)

// Scratch (allocation-free: __device__ globals)
__device__ float g_mlp[BN * HO];
__device__ float g_z[BN * HO];
__device__ float g_xp[BN * HO];
__device__ float g_sT[Bb * Hh * Nn];
__device__ float g_ngT[Bb * Hh * Nn];
__device__ float g_mx[Bb * Hh * Nn];
__device__ float g_isum[Bb * Hh * Nn];

// ---------------------------------------------------------------------------
// GEMM with K=256, ldA=ldC=256, W row-major [256][256].
// EPI=0: C = sigmoid(acc + bvec[col])   (MLP)
// EPI=1: C = acc                        (xp = z @ kernel)
// Tile 64x64, ktile 16, 256 threads, 4x4 per thread.
// ---------------------------------------------------------------------------
template <int EPI>
__global__ void gemm_k256(const float* __restrict__ A,
                          const float* __restrict__ W,
                          const float* __restrict__ bvec,
                          float* __restrict__ C, int M)
{
    __shared__ float As[16][68];
    __shared__ float Bs[16][68];
    const int t = threadIdx.x;
    const int row0 = blockIdx.x * 64;
    const int col0 = blockIdx.y * 64;
    const int tx = t & 15;        // col group
    const int ty = t >> 4;        // row group

    float acc[4][4] = {};

    for (int k0 = 0; k0 < 256; k0 += 16) {
        // A tile: As[kk][row]
        #pragma unroll
        for (int i = 0; i < 4; i++) {
            int r = (t >> 4) + i * 16;
            int kk = t & 15;
            int gr = row0 + r;
            As[kk][r] = (gr < M) ? A[gr * 256 + k0 + kk] : 0.0f;
        }
        // B tile: Bs[kk][col]
        #pragma unroll
        for (int i = 0; i < 4; i++) {
            int kk = (t >> 6) + i * 4;
            int c = t & 63;
            Bs[kk][c] = W[(k0 + kk) * 256 + col0 + c];
        }
        __syncthreads();
        #pragma unroll
        for (int kk = 0; kk < 16; kk++) {
            float a4[4], b4[4];
            *(float4*)a4 = *(const float4*)&As[kk][ty * 4];
            *(float4*)b4 = *(const float4*)&Bs[kk][tx * 4];
            #pragma unroll
            for (int i = 0; i < 4; i++)
                #pragma unroll
                for (int j = 0; j < 4; j++)
                    acc[i][j] += a4[i] * b4[j];
        }
        __syncthreads();
    }

    #pragma unroll
    for (int i = 0; i < 4; i++) {
        int gr = row0 + ty * 4 + i;
        if (gr >= M) continue;
        #pragma unroll
        for (int j = 0; j < 4; j++) {
            int gc = col0 + tx * 4 + j;
            float v = acc[i][j];
            if (EPI == 0) {
                v += bvec[gc];
                v = 1.0f / (1.0f + __expf(-v));
            }
            C[gr * 256 + gc] = v;
        }
    }
}

// ---------------------------------------------------------------------------
// z[b] = (1-alpha) * a @ mlp[b] + alpha * mlp[b]
// M=N=392 rows, K=392, 64x64 tile.
// grid: (colTiles=4, rowTiles=7, B)
// ---------------------------------------------------------------------------
__global__ void gemm_prop(const float* __restrict__ Aadj,
                          const float* __restrict__ Mlp,
                          float* __restrict__ Z)
{
    __shared__ float As[16][68];
    __shared__ float Bs[16][68];
    const int b = blockIdx.z;
    const int row0 = blockIdx.y * 64;
    const int col0 = blockIdx.x * 64;
    const float* Bm = Mlp + (size_t)b * Nn * HO;
    const int t = threadIdx.x;
    const int tx = t & 15;
    const int ty = t >> 4;

    float acc[4][4] = {};

    for (int k0 = 0; k0 < Nn; k0 += 16) {
        #pragma unroll
        for (int i = 0; i < 4; i++) {
            int r = (t >> 4) + i * 16;
            int kk = t & 15;
            int gr = row0 + r;
            int gk = k0 + kk;
            As[kk][r] = (gr < Nn && gk < Nn) ? Aadj[gr * Nn + gk] : 0.0f;
        }
        #pragma unroll
        for (int i = 0; i < 4; i++) {
            int kk = (t >> 6) + i * 4;
            int c = t & 63;
            int gk = k0 + kk;
            Bs[kk][c] = (gk < Nn) ? Bm[gk * 256 + col0 + c] : 0.0f;
        }
        __syncthreads();
        #pragma unroll
        for (int kk = 0; kk < 16; kk++) {
            float a4[4], b4[4];
            *(float4*)a4 = *(const float4*)&As[kk][ty * 4];
            *(float4*)b4 = *(const float4*)&Bs[kk][tx * 4];
            #pragma unroll
            for (int i = 0; i < 4; i++)
                #pragma unroll
                for (int j = 0; j < 4; j++)
                    acc[i][j] += a4[i] * b4[j];
        }
        __syncthreads();
    }

    #pragma unroll
    for (int i = 0; i < 4; i++) {
        int gr = row0 + ty * 4 + i;
        if (gr >= Nn) continue;
        #pragma unroll
        for (int j = 0; j < 4; j++) {
            int gc = col0 + tx * 4 + j;
            float v = (1.0f - ALPHA_C) * acc[i][j] + ALPHA_C * Bm[gr * 256 + gc];
            Z[((size_t)b * Nn + gr) * 256 + gc] = v;
        }
    }
}

// ---------------------------------------------------------------------------
// s[b,n,h] = sum_o xp[b,n,h,o] * ak_self[o,h] ; same for ng.
// stored transposed: sT[(b*H+h)*N + n]. One warp per (b,n).
// ---------------------------------------------------------------------------
__global__ void k_proj(const float* __restrict__ xp,
                       const float* __restrict__ ak_self,
                       const float* __restrict__ ak_neigh,
                       float* __restrict__ sT, float* __restrict__ ngT)
{
    int gw = (blockIdx.x * blockDim.x + threadIdx.x) >> 5;
    int lane = threadIdx.x & 31;
    if (gw >= BN) return;
    int b = gw / Nn, n = gw - b * Nn;
    const float* xr = xp + (size_t)gw * HO;
    #pragma unroll
    for (int h = 0; h < Hh; h++) {
        float v0 = xr[h * 64 + lane];
        float v1 = xr[h * 64 + 32 + lane];
        float ss = v0 * ak_self[lane * Hh + h] + v1 * ak_self[(lane + 32) * Hh + h];
        float ng = v0 * ak_neigh[lane * Hh + h] + v1 * ak_neigh[(lane + 32) * Hh + h];
        #pragma unroll
        for (int off = 16; off > 0; off >>= 1) {
            ss += __shfl_down_sync(0xffffffffu, ss, off);
            ng += __shfl_down_sync(0xffffffffu, ng, off);
        }
        if (lane == 0) {
            sT[(b * Hh + h) * Nn + n] = ss;
            ngT[(b * Hh + h) * Nn + n] = ng;
        }
    }
}

// ---------------------------------------------------------------------------
// Softmax row statistics: mx[b,h,n], isum[b,h,n] over the m axis.
// grid (N, B), block 128 = 4 warps (one per head).
// ---------------------------------------------------------------------------
__global__ void k_stats(const float* __restrict__ Aadj,
                        const float* __restrict__ sT,
                        const float* __restrict__ ngT,
                        float* __restrict__ mx, float* __restrict__ isum)
{
    const int n = blockIdx.x, b = blockIdx.y;
    const int h = threadIdx.x >> 5, lane = threadIdx.x & 31;
    const int bh = b * Hh + h;
    const float sv = sT[bh * Nn + n];
    const float* ngr = ngT + (size_t)bh * Nn;
    const float* ar = Aadj + (size_t)n * Nn;

    float lv[13];
    float m = -3.0e38f;
    #pragma unroll
    for (int it = 0; it < 13; it++) {
        int mm = lane + it * 32;
        float l = -3.0e38f;
        if (mm < Nn) {
            float l0 = sv + ngr[mm];
            l = (l0 > 0.0f) ? l0 : LEAKY_C * l0;
            float av = (mm == n) ? 1.0f : ar[mm];
            if (av == 0.0f) l += NEG_INF_C;
        }
        lv[it] = l;
        m = fmaxf(m, l);
    }
    #pragma unroll
    for (int off = 16; off > 0; off >>= 1)
        m = fmaxf(m, __shfl_xor_sync(0xffffffffu, m, off));

    float s = 0.0f;
    #pragma unroll
    for (int it = 0; it < 13; it++) {
        int mm = lane + it * 32;
        if (mm < Nn) s += __expf(lv[it] - m);
    }
    #pragma unroll
    for (int off = 16; off > 0; off >>= 1)
        s += __shfl_xor_sync(0xffffffffu, s, off);

    if (lane == 0) {
        mx[bh * Nn + n] = m;
        isum[bh * Nn + n] = 1.0f / s;
    }
}

// ---------------------------------------------------------------------------
// AV: out[b,n,h,:] = sum_m P(b,h,n,m) * xp[b,m,h,:]  (+bias, ELU)
// P recomputed in tiles (32 rows x 32 m) in shared.
// grid: (rowTiles=13, H, B), 256 threads, 2x4 microtile.
// ---------------------------------------------------------------------------
__global__ void k_av(const float* __restrict__ xp,
                     const float* __restrict__ Aadj,
                     const float* __restrict__ sT,
                     const float* __restrict__ ngT,
                     const float* __restrict__ mx,
                     const float* __restrict__ isum,
                     const float* __restrict__ bias,
                     float* __restrict__ out)
{
    const int n0 = blockIdx.x * 32;
    const int h = blockIdx.y, b = blockIdx.z;
    const int bh = b * Hh + h;
    __shared__ float xpS[32 * 64];
    __shared__ float Ps[32 * 33];
    __shared__ float sSh[32], mSh[32], iSh[32];
    const int t = threadIdx.x;

    if (t < 32) {
        int n = n0 + t;
        bool v = (n < Nn);
        sSh[t] = v ? sT[bh * Nn + n] : 0.0f;
        mSh[t] = v ? mx[bh * Nn + n] : 0.0f;
        iSh[t] = v ? isum[bh * Nn + n] : 0.0f;
    }
    __syncthreads();

    const int cx = t & 15;        // col group: cols cx*4 .. cx*4+3
    const int cy = t >> 4;        // rows cy and cy+16
    float acc[2][4] = {};

    for (int m0 = 0; m0 < Nn; m0 += 32) {
        // Load xp chunk [32 m][64 o]
        #pragma unroll
        for (int i = 0; i < 8; i++) {
            int mm = (t >> 6) + i * 4;
            int c = t & 63;
            int gm = m0 + mm;
            xpS[mm * 64 + c] =
                (gm < Nn) ? xp[((size_t)(b * Nn + gm)) * 256 + h * 64 + c] : 0.0f;
        }
        // Compute P tile [32 rows][32 m]
        #pragma unroll
        for (int i = 0; i < 4; i++) {
            int idx = t + i * 256;
            int r = idx >> 5, mi = idx & 31;
            int gm = m0 + mi, gn = n0 + r;
            float p = 0.0f;
            if (gm < Nn && gn < Nn) {
                float l0 = sSh[r] + ngT[(size_t)bh * Nn + gm];
                float l = (l0 > 0.0f) ? l0 : LEAKY_C * l0;
                float av = (gm == gn) ? 1.0f : Aadj[(size_t)gn * Nn + gm];
                if (av == 0.0f) l += NEG_INF_C;
                p = __expf(l - mSh[r]) * iSh[r];
            }
            Ps[r * 33 + mi] = p;
        }
        __syncthreads();
        #pragma unroll
        for (int mm = 0; mm < 32; mm++) {
            float a0 = Ps[cy * 33 + mm];
            float a1 = Ps[(cy + 16) * 33 + mm];
            float4 bv = *(const float4*)&xpS[mm * 64 + cx * 4];
            acc[0][0] += a0 * bv.x; acc[0][1] += a0 * bv.y;
            acc[0][2] += a0 * bv.z; acc[0][3] += a0 * bv.w;
            acc[1][0] += a1 * bv.x; acc[1][1] += a1 * bv.y;
            acc[1][2] += a1 * bv.z; acc[1][3] += a1 * bv.w;
        }
        __syncthreads();
    }

    #pragma unroll
    for (int i = 0; i < 2; i++) {
        int n = n0 + cy + i * 16;
        if (n >= Nn) continue;
        #pragma unroll
        for (int j = 0; j < 4; j++) {
            int c = h * 64 + cx * 4 + j;
            float v = acc[i][j] + bias[c];
            v = (v > 0.0f) ? v : expm1f(v);   // ELU (alpha=1)
            out[((size_t)(b * Nn + n)) * 256 + c] = v;
        }
    }
}

// ---------------------------------------------------------------------------
extern "C" void kernel_launch(void* const* d_in, const int* in_sizes, int n_in,
                              void* d_out, int out_size)
{
    const float* x        = (const float*)d_in[0];  // [B,N,I]
    const float* a        = (const float*)d_in[1];  // [N,N]
    const float* w_mlp    = (const float*)d_in[2];  // [I,I]
    const float* b_mlp    = (const float*)d_in[3];  // [I]
    const float* kern     = (const float*)d_in[4];  // [I,H,O] == [256][256]
    const float* ak_self  = (const float*)d_in[5];  // [O,H,1]
    const float* ak_neigh = (const float*)d_in[6];  // [O,H,1]
    const float* bias     = (const float*)d_in[7];  // [H*O]
    float* out = (float*)d_out;

    float *p_mlp, *p_z, *p_xp, *p_sT, *p_ngT, *p_mx, *p_isum;
    cudaGetSymbolAddress((void**)&p_mlp, g_mlp);
    cudaGetSymbolAddress((void**)&p_z, g_z);
    cudaGetSymbolAddress((void**)&p_xp, g_xp);
    cudaGetSymbolAddress((void**)&p_sT, g_sT);
    cudaGetSymbolAddress((void**)&p_ngT, g_ngT);
    cudaGetSymbolAddress((void**)&p_mx, g_mx);
    cudaGetSymbolAddress((void**)&p_isum, g_isum);

    // 1. mlp_out = sigmoid(x @ w_mlp + b)
    gemm_k256<0><<<dim3((BN + 63) / 64, 4), 256>>>(x, w_mlp, b_mlp, p_mlp, BN);
    // 2. z = (1-a)*adj@mlp + a*mlp (per batch)
    gemm_prop<<<dim3(4, (Nn + 63) / 64, Bb), 256>>>(a, p_mlp, p_z);
    // 3. xp = z @ kernel
    gemm_k256<1><<<dim3((BN + 63) / 64, 4), 256>>>(p_z, kern, nullptr, p_xp, BN);
    // 4. s / ng projections
    k_proj<<<(BN * 32 + 255) / 256, 256>>>(p_xp, ak_self, ak_neigh, p_sT, p_ngT);
    // 5. softmax stats
    k_stats<<<dim3(Nn, Bb), 128>>>(a, p_sT, p_ngT, p_mx, p_isum);
    // 6. AV + bias + ELU
    k_av<<<dim3((Nn + 31) / 32, Hh, Bb), 256>>>(p_xp, a, p_sT, p_ngT, p_mx, p_isum,
                                                bias, out);
}

// round 3
// speedup vs baseline: 1.5630x; 1.5630x over previous
#include <cuda_runtime.h>
#include <cstdint>

// Problem constants
constexpr int Bb = 108;
constexpr int Nn = 392;
constexpr int Hh = 4;
constexpr int HO = 256;         // H*O
constexpr int BN = Bb * Nn;     // 42336

#define ALPHA_C   0.2f
#define LEAKY_C   0.2f

// Scratch (allocation-free: __device__ globals)
__device__ float g_mlp[BN * HO];
__device__ float g_mlpT[BN * HO];
__device__ float g_z[BN * HO];
__device__ float g_xp[BN * HO];
__device__ float g_wT[256 * 256];
__device__ float g_kT[256 * 256];
__device__ float g_sT[Bb * Hh * Nn];
__device__ float g_ngT[Bb * Hh * Nn];
__device__ float g_mx[Bb * Hh * Nn];
__device__ float g_isum[Bb * Hh * Nn];
__device__ unsigned g_mbits[Nn * 13];

// ---------------------------------------------------------------------------
// mma.sync tf32 helpers (sm_80+ PTX; compiles for plain compute_103)
// ---------------------------------------------------------------------------
__device__ __forceinline__ uint32_t f2tf(float f) {
    uint32_t r;
    asm("cvt.rna.tf32.f32 %0, %1;" : "=r"(r) : "f"(f));
    return r;
}
__device__ __forceinline__ void mma_tf32(float* c, const uint32_t* a,
                                         uint32_t b0, uint32_t b1) {
    asm volatile(
        "mma.sync.aligned.m16n8k8.row.col.f32.tf32.tf32.f32 "
        "{%0,%1,%2,%3}, {%4,%5,%6,%7}, {%8,%9}, {%0,%1,%2,%3};"
        : "+f"(c[0]), "+f"(c[1]), "+f"(c[2]), "+f"(c[3])
        : "r"(a[0]), "r"(a[1]), "r"(a[2]), "r"(a[3]), "r"(b0), "r"(b1));
}

// SMEM: double-buffered stages. Each stage: A[128][36] + B[128][36] floats.
constexpr int TSTRIDE = 36;                      // 36 mod 32 = 4 -> conflict-free frags
constexpr int STAGE_FLOATS = 128 * TSTRIDE;      // 4608 floats per tile
constexpr unsigned SMEM_TC = 2u * 2u * STAGE_FLOATS * 4u;  // 73728 bytes

// ---------------------------------------------------------------------------
// tf32 mma GEMM: C[M,256] = A[M,K] @ B^T, B stored [256][K] k-major.
// EPI 0: sigmoid(acc + extra[col])      (MLP)
// EPI 1: plain                           (xp)
// EPI 2: 0.8*acc + 0.2*extra[row,col]    (APPNP propagate)
// grid: (ceil(M/128), 2, batches); 128 threads (4 warps, 2x2 of 64x64)
// ---------------------------------------------------------------------------
template <int EPI>
__global__ void __launch_bounds__(128)
tc_gemm(const float* __restrict__ A, long strideA,
        const float* __restrict__ Bm, long strideB,
        const float* __restrict__ extra, long strideE,
        float* __restrict__ C, long strideC,
        int M, int K, int S)
{
    extern __shared__ float smem[];
    const int t = threadIdx.x;
    const int m0 = blockIdx.x * 128;
    const int col0 = blockIdx.y * 128;
    A += (size_t)blockIdx.z * strideA;
    Bm += (size_t)blockIdx.z * strideB;
    extra += (size_t)blockIdx.z * strideE;
    C += (size_t)blockIdx.z * strideC;

    const int w = t >> 5, lane = t & 31;
    const int g = lane >> 2, tg = lane & 3;
    const int warpM = (w & 1) * 64, warpN = (w >> 1) * 64;

    float acc[4][8][4];
    #pragma unroll
    for (int i = 0; i < 4; i++)
        #pragma unroll
        for (int j = 0; j < 8; j++)
            #pragma unroll
            for (int q = 0; q < 4; q++) acc[i][j][q] = 0.0f;

    auto stage = [&](int s, int p) {
        const int k0 = s * 32;
        float* As = smem + p * 2 * STAGE_FLOATS;
        float* Bs = As + STAGE_FLOATS;
        #pragma unroll
        for (int i = 0; i < 8; i++) {
            int idx = t + i * 128;
            int row = idx >> 3, q = idx & 7;
            int gr = m0 + row, k = k0 + q * 4;
            float4 v = make_float4(0.f, 0.f, 0.f, 0.f);
            if (gr < M && k < K) v = *(const float4*)(A + (size_t)gr * K + k);
            float4 c4;
            c4.x = __uint_as_float(f2tf(v.x));
            c4.y = __uint_as_float(f2tf(v.y));
            c4.z = __uint_as_float(f2tf(v.z));
            c4.w = __uint_as_float(f2tf(v.w));
            *(float4*)(As + row * TSTRIDE + q * 4) = c4;
        }
        #pragma unroll
        for (int i = 0; i < 8; i++) {
            int idx = t + i * 128;
            int row = idx >> 3, q = idx & 7;
            int k = k0 + q * 4;
            float4 v = make_float4(0.f, 0.f, 0.f, 0.f);
            if (k < K) v = *(const float4*)(Bm + (size_t)(col0 + row) * K + k);
            float4 c4;
            c4.x = __uint_as_float(f2tf(v.x));
            c4.y = __uint_as_float(f2tf(v.y));
            c4.z = __uint_as_float(f2tf(v.z));
            c4.w = __uint_as_float(f2tf(v.w));
            *(float4*)(Bs + row * TSTRIDE + q * 4) = c4;
        }
    };

    auto compute = [&](int p) {
        const uint32_t* As = (const uint32_t*)(smem + p * 2 * STAGE_FLOATS);
        const uint32_t* Bs = As + STAGE_FLOATS;
        #pragma unroll
        for (int ks = 0; ks < 4; ks++) {
            const int kb = ks * 8;
            uint32_t af[4][4];
            #pragma unroll
            for (int mt = 0; mt < 4; mt++) {
                const int r = warpM + mt * 16;
                af[mt][0] = As[(r + g) * TSTRIDE + kb + tg];
                af[mt][1] = As[(r + g + 8) * TSTRIDE + kb + tg];
                af[mt][2] = As[(r + g) * TSTRIDE + kb + tg + 4];
                af[mt][3] = As[(r + g + 8) * TSTRIDE + kb + tg + 4];
            }
            #pragma unroll
            for (int nt = 0; nt < 8; nt++) {
                const int c = warpN + nt * 8 + g;
                uint32_t b0 = Bs[c * TSTRIDE + kb + tg];
                uint32_t b1 = Bs[c * TSTRIDE + kb + tg + 4];
                #pragma unroll
                for (int mt = 0; mt < 4; mt++)
                    mma_tf32(acc[mt][nt], af[mt], b0, b1);
            }
        }
    };

    stage(0, 0);
    __syncthreads();
    for (int s = 0; s < S; s++) {
        const int p = s & 1;
        if (s + 1 < S) stage(s + 1, p ^ 1);
        compute(p);
        __syncthreads();
    }

    // Epilogue
    #pragma unroll
    for (int mt = 0; mt < 4; mt++) {
        #pragma unroll
        for (int half = 0; half < 2; half++) {
            int r = m0 + warpM + mt * 16 + g + half * 8;
            if (r >= M) continue;
            #pragma unroll
            for (int nt = 0; nt < 8; nt++) {
                int cc = col0 + warpN + nt * 8 + tg * 2;
                float v0 = acc[mt][nt][half * 2 + 0];
                float v1 = acc[mt][nt][half * 2 + 1];
                float2 o;
                if (EPI == 0) {
                    float2 bb = *(const float2*)(extra + cc);
                    o.x = 1.0f / (1.0f + __expf(-(v0 + bb.x)));
                    o.y = 1.0f / (1.0f + __expf(-(v1 + bb.y)));
                } else if (EPI == 2) {
                    float2 e = *(const float2*)(extra + (size_t)r * 256 + cc);
                    o.x = (1.0f - ALPHA_C) * v0 + ALPHA_C * e.x;
                    o.y = (1.0f - ALPHA_C) * v1 + ALPHA_C * e.y;
                } else {
                    o.x = v0; o.y = v1;
                }
                *(float2*)(C + (size_t)r * 256 + cc) = o;
            }
        }
    }
}

// ---------------------------------------------------------------------------
// Tiled transpose: in [R][C] -> out [C][R], batched via blockIdx.z
// ---------------------------------------------------------------------------
__global__ void k_transpose(const float* __restrict__ in, float* __restrict__ out,
                            int R, int C, long sIn, long sOut)
{
    __shared__ float tile[32][33];
    in += (size_t)blockIdx.z * sIn;
    out += (size_t)blockIdx.z * sOut;
    int c = blockIdx.x * 32 + threadIdx.x;
    int r = blockIdx.y * 32 + threadIdx.y;
    #pragma unroll
    for (int i = 0; i < 4; i++) {
        int rr = r + i * 8;
        if (rr < R && c < C) tile[threadIdx.y + i * 8][threadIdx.x] = in[(size_t)rr * C + c];
    }
    __syncthreads();
    int c2 = blockIdx.y * 32 + threadIdx.x;
    int r2 = blockIdx.x * 32 + threadIdx.y;
    #pragma unroll
    for (int i = 0; i < 4; i++) {
        int rr = r2 + i * 8;
        if (rr < C && c2 < R) out[(size_t)rr * R + c2] = tile[threadIdx.x][threadIdx.y + i * 8];
    }
}

// ---------------------------------------------------------------------------
// Mask bitmap: bit set where (a[n][m]==0 && m!=n)  => masked-out logit
// ---------------------------------------------------------------------------
__global__ void k_mask(const float* __restrict__ a, unsigned* __restrict__ mb)
{
    int i = blockIdx.x * blockDim.x + threadIdx.x;
    if (i >= Nn * 13) return;
    int n = i / 13, w = i - n * 13;
    unsigned bits = 0;
    #pragma unroll
    for (int j = 0; j < 32; j++) {
        int m = w * 32 + j;
        if (m < Nn && m != n && a[(size_t)n * Nn + m] == 0.0f) bits |= 1u << j;
    }
    mb[i] = bits;
}

// ---------------------------------------------------------------------------
// s/ng projections (one warp per (b,n))
// ---------------------------------------------------------------------------
__global__ void k_proj(const float* __restrict__ xp,
                       const float* __restrict__ ak_self,
                       const float* __restrict__ ak_neigh,
                       float* __restrict__ sT, float* __restrict__ ngT)
{
    int gw = (blockIdx.x * blockDim.x + threadIdx.x) >> 5;
    int lane = threadIdx.x & 31;
    if (gw >= BN) return;
    int b = gw / Nn, n = gw - b * Nn;
    const float* xr = xp + (size_t)gw * HO;
    #pragma unroll
    for (int h = 0; h < Hh; h++) {
        float v0 = xr[h * 64 + lane];
        float v1 = xr[h * 64 + 32 + lane];
        float ss = v0 * ak_self[lane * Hh + h] + v1 * ak_self[(lane + 32) * Hh + h];
        float ng = v0 * ak_neigh[lane * Hh + h] + v1 * ak_neigh[(lane + 32) * Hh + h];
        #pragma unroll
        for (int off = 16; off > 0; off >>= 1) {
            ss += __shfl_down_sync(0xffffffffu, ss, off);
            ng += __shfl_down_sync(0xffffffffu, ng, off);
        }
        if (lane == 0) {
            sT[(b * Hh + h) * Nn + n] = ss;
            ngT[(b * Hh + h) * Nn + n] = ng;
        }
    }
}

// ---------------------------------------------------------------------------
// Softmax stats (bitmask; masked entries excluded exactly)
// ---------------------------------------------------------------------------
__global__ void k_stats(const unsigned* __restrict__ mb,
                        const float* __restrict__ sT,
                        const float* __restrict__ ngT,
                        float* __restrict__ mx, float* __restrict__ isum)
{
    const int n = blockIdx.x, b = blockIdx.y;
    const int h = threadIdx.x >> 5, lane = threadIdx.x & 31;
    const int bh = b * Hh + h;
    const float sv = sT[bh * Nn + n];
    const float* ngr = ngT + (size_t)bh * Nn;

    float lv[13];
    float m = -3.0e38f;
    #pragma unroll
    for (int it = 0; it < 13; it++) {
        int mm = lane + it * 32;
        unsigned wd = mb[n * 13 + it];
        float l = -3.0e38f;
        if (mm < Nn && !((wd >> lane) & 1u)) {
            float l0 = sv + ngr[mm];
            l = (l0 > 0.0f) ? l0 : LEAKY_C * l0;
        }
        lv[it] = l;
        m = fmaxf(m, l);
    }
    #pragma unroll
    for (int off = 16; off > 0; off >>= 1)
        m = fmaxf(m, __shfl_xor_sync(0xffffffffu, m, off));

    float s = 0.0f;
    #pragma unroll
    for (int it = 0; it < 13; it++) {
        if (lv[it] > -1.0e38f) s += __expf(lv[it] - m);
    }
    #pragma unroll
    for (int off = 16; off > 0; off >>= 1)
        s += __shfl_xor_sync(0xffffffffu, s, off);

    if (lane == 0) {
        mx[bh * Nn + n] = m;
        isum[bh * Nn + n] = 1.0f / s;
    }
}

// ---------------------------------------------------------------------------
// AV: out[b,n,h,:] = sum_m P(b,h,n,m) * xp[b,m,h,:]  (+bias, ELU)
// 64-row x 64-col tile, 32-m stage, transposed P staging.
// ---------------------------------------------------------------------------
__global__ void k_av(const float* __restrict__ xp,
                     const unsigned* __restrict__ mb,
                     const float* __restrict__ sT,
                     const float* __restrict__ ngT,
                     const float* __restrict__ mx,
                     const float* __restrict__ isum,
                     const float* __restrict__ bias,
                     float* __restrict__ out)
{
    const int n0 = blockIdx.x * 64;
    const int h = blockIdx.y, b = blockIdx.z;
    const int bh = b * Hh + h;
    __shared__ float xpS[32 * 64];
    __shared__ float PsT[32 * 68];     // [m][r], r padded to 68
    __shared__ float sSh[64], mSh[64], iSh[64], ngS[32];
    const int t = threadIdx.x;

    if (t < 64) {
        int n = n0 + t;
        bool v = (n < Nn);
        sSh[t] = v ? sT[bh * Nn + n] : 0.0f;
        mSh[t] = v ? mx[bh * Nn + n] : 0.0f;
        iSh[t] = v ? isum[bh * Nn + n] : 0.0f;
    }
    __syncthreads();

    const int tx = t & 15;        // cols tx*4 .. +3
    const int ty = t >> 4;        // rows ty*4 .. +3
    float acc[4][4] = {};

    for (int m0 = 0; m0 < Nn; m0 += 32) {
        if (t < 32) {
            int gm = m0 + t;
            ngS[t] = (gm < Nn) ? ngT[(size_t)bh * Nn + gm] : 0.0f;
        }
        #pragma unroll
        for (int i = 0; i < 2; i++) {
            int idx = t + i * 256;
            int mm = idx >> 4, q = idx & 15;
            int gm = m0 + mm;
            float4 v = make_float4(0.f, 0.f, 0.f, 0.f);
            if (gm < Nn)
                v = *(const float4*)(xp + ((size_t)(b * Nn + gm)) * 256 + h * 64 + q * 4);
            *(float4*)&xpS[mm * 64 + q * 4] = v;
        }
        __syncthreads();
        #pragma unroll
        for (int i = 0; i < 8; i++) {
            int e = t + i * 256;
            int mi = e >> 6, r = e & 63;
            int gm = m0 + mi, gn = n0 + r;
            float p = 0.0f;
            if (gm < Nn && gn < Nn) {
                bool msk = (mb[gn * 13 + (gm >> 5)] >> (gm & 31)) & 1u;
                if (!msk) {
                    float l0 = sSh[r] + ngS[mi];
                    float l = (l0 > 0.0f) ? l0 : LEAKY_C * l0;
                    p = __expf(l - mSh[r]) * iSh[r];
                }
            }
            PsT[mi * 68 + r] = p;
        }
        __syncthreads();
        #pragma unroll
        for (int mm = 0; mm < 32; mm++) {
            float4 pr = *(const float4*)&PsT[mm * 68 + ty * 4];
            float4 xv = *(const float4*)&xpS[mm * 64 + tx * 4];
            acc[0][0] += pr.x * xv.x; acc[0][1] += pr.x * xv.y;
            acc[0][2] += pr.x * xv.z; acc[0][3] += pr.x * xv.w;
            acc[1][0] += pr.y * xv.x; acc[1][1] += pr.y * xv.y;
            acc[1][2] += pr.y * xv.z; acc[1][3] += pr.y * xv.w;
            acc[2][0] += pr.z * xv.x; acc[2][1] += pr.z * xv.y;
            acc[2][2] += pr.z * xv.z; acc[2][3] += pr.z * xv.w;
            acc[3][0] += pr.w * xv.x; acc[3][1] += pr.w * xv.y;
            acc[3][2] += pr.w * xv.z; acc[3][3] += pr.w * xv.w;
        }
        __syncthreads();
    }

    #pragma unroll
    for (int i = 0; i < 4; i++) {
        int n = n0 + ty * 4 + i;
        if (n >= Nn) continue;
        int c = h * 64 + tx * 4;
        float4 bb = *(const float4*)(bias + c);
        float4 v;
        v.x = acc[i][0] + bb.x; v.y = acc[i][1] + bb.y;
        v.z = acc[i][2] + bb.z; v.w = acc[i][3] + bb.w;
        v.x = (v.x > 0.0f) ? v.x : expm1f(v.x);
        v.y = (v.y > 0.0f) ? v.y : expm1f(v.y);
        v.z = (v.z > 0.0f) ? v.z : expm1f(v.z);
        v.w = (v.w > 0.0f) ? v.w : expm1f(v.w);
        *(float4*)(out + ((size_t)(b * Nn + n)) * 256 + c) = v;
    }
}

// ---------------------------------------------------------------------------
extern "C" void kernel_launch(void* const* d_in, const int* in_sizes, int n_in,
                              void* d_out, int out_size)
{
    const float* x        = (const float*)d_in[0];
    const float* a        = (const float*)d_in[1];
    const float* w_mlp    = (const float*)d_in[2];
    const float* b_mlp    = (const float*)d_in[3];
    const float* kern     = (const float*)d_in[4];
    const float* ak_self  = (const float*)d_in[5];
    const float* ak_neigh = (const float*)d_in[6];
    const float* bias     = (const float*)d_in[7];
    float* out = (float*)d_out;

    float *p_mlp, *p_mlpT, *p_z, *p_xp, *p_wT, *p_kT, *p_sT, *p_ngT, *p_mx, *p_isum;
    unsigned* p_mbits;
    cudaGetSymbolAddress((void**)&p_mlp, g_mlp);
    cudaGetSymbolAddress((void**)&p_mlpT, g_mlpT);
    cudaGetSymbolAddress((void**)&p_z, g_z);
    cudaGetSymbolAddress((void**)&p_xp, g_xp);
    cudaGetSymbolAddress((void**)&p_wT, g_wT);
    cudaGetSymbolAddress((void**)&p_kT, g_kT);
    cudaGetSymbolAddress((void**)&p_sT, g_sT);
    cudaGetSymbolAddress((void**)&p_ngT, g_ngT);
    cudaGetSymbolAddress((void**)&p_mx, g_mx);
    cudaGetSymbolAddress((void**)&p_isum, g_isum);
    cudaGetSymbolAddress((void**)&p_mbits, g_mbits);

    cudaFuncSetAttribute(tc_gemm<0>, cudaFuncAttributeMaxDynamicSharedMemorySize, SMEM_TC);
    cudaFuncSetAttribute(tc_gemm<1>, cudaFuncAttributeMaxDynamicSharedMemorySize, SMEM_TC);
    cudaFuncSetAttribute(tc_gemm<2>, cudaFuncAttributeMaxDynamicSharedMemorySize, SMEM_TC);

    // transposed weights + mask bitmap
    k_transpose<<<dim3(8, 8, 1), dim3(32, 8)>>>(w_mlp, p_wT, 256, 256, 0, 0);
    k_transpose<<<dim3(8, 8, 1), dim3(32, 8)>>>(kern, p_kT, 256, 256, 0, 0);
    k_mask<<<(Nn * 13 + 127) / 128, 128>>>(a, p_mbits);

    // 1. mlp = sigmoid(x @ w_mlp + b)      [tf32 mma]
    tc_gemm<0><<<dim3((BN + 127) / 128, 2, 1), 128, SMEM_TC>>>(
        x, 0, p_wT, 0, b_mlp, 0, p_mlp, 0, BN, 256, 8);
    // 2. mlpT per batch
    k_transpose<<<dim3(8, 13, Bb), dim3(32, 8)>>>(p_mlp, p_mlpT, Nn, 256,
                                                  (long)Nn * 256, (long)Nn * 256);
    // 3. z = 0.8 * adj @ mlp + 0.2 * mlp   [tf32 mma]
    tc_gemm<2><<<dim3(4, 2, Bb), 128, SMEM_TC>>>(
        a, 0, p_mlpT, (long)Nn * 256, p_mlp, (long)Nn * 256, p_z, (long)Nn * 256,
        Nn, Nn, 13);
    // 4. xp = z @ kernel                   [tf32 mma]
    tc_gemm<1><<<dim3((BN + 127) / 128, 2, 1), 128, SMEM_TC>>>(
        p_z, 0, p_kT, 0, nullptr, 0, p_xp, 0, BN, 256, 8);
    // 5. s / ng projections
    k_proj<<<(BN * 32 + 255) / 256, 256>>>(p_xp, ak_self, ak_neigh, p_sT, p_ngT);
    // 6. softmax stats
    k_stats<<<dim3(Nn, Bb), 128>>>(p_mbits, p_sT, p_ngT, p_mx, p_isum);
    // 7. AV + bias + ELU
    k_av<<<dim3((Nn + 63) / 64, Hh, Bb), 256>>>(p_xp, p_mbits, p_sT, p_ngT,
                                                p_mx, p_isum, bias, out);
}

// round 4
// speedup vs baseline: 1.6007x; 1.0241x over previous
#include <cuda_runtime.h>
#include <cstdint>

// Problem constants
constexpr int Bb = 108;
constexpr int Nn = 392;
constexpr int Hh = 4;
constexpr int HO = 256;         // H*O
constexpr int BN = Bb * Nn;     // 42336

#define ALPHA_C   0.2f
#define LEAKY_C   0.2f

// Scratch (allocation-free: __device__ globals)
__device__ float g_mlp[BN * HO];
__device__ float g_mlpT[BN * HO];
__device__ float g_z[BN * HO];
__device__ float g_xp[BN * HO];
__device__ float g_wT[256 * 256];
__device__ float g_kT[256 * 256];
__device__ float g_sT[Bb * Hh * Nn];
__device__ float g_ngT[Bb * Hh * Nn];
__device__ float g_mx[Bb * Hh * Nn];
__device__ float g_isum[Bb * Hh * Nn];
__device__ unsigned g_mbits[Nn * 13];

// ---------------------------------------------------------------------------
// mma.sync tf32 helpers
// ---------------------------------------------------------------------------
__device__ __forceinline__ uint32_t f2tf(float f) {
    uint32_t r;
    asm("cvt.rna.tf32.f32 %0, %1;" : "=r"(r) : "f"(f));
    return r;
}
__device__ __forceinline__ void mma_tf32(float* c, const uint32_t* a,
                                         uint32_t b0, uint32_t b1) {
    asm volatile(
        "mma.sync.aligned.m16n8k8.row.col.f32.tf32.tf32.f32 "
        "{%0,%1,%2,%3}, {%4,%5,%6,%7}, {%8,%9}, {%0,%1,%2,%3};"
        : "+f"(c[0]), "+f"(c[1]), "+f"(c[2]), "+f"(c[3])
        : "r"(a[0]), "r"(a[1]), "r"(a[2]), "r"(a[3]), "r"(b0), "r"(b1));
}

// SMEM: double-buffered stages. Each stage: A[128][36] + B[128][36] floats.
constexpr int TSTRIDE = 36;                      // 36 mod 32 = 4 -> conflict-free frags
constexpr int STAGE_FLOATS = 128 * TSTRIDE;
constexpr unsigned SMEM_TC = 2u * 2u * STAGE_FLOATS * 4u;  // 73728 bytes

// ---------------------------------------------------------------------------
// tf32 mma GEMM: C[M,256] = A[M,K] @ B^T, B stored [256][K] k-major.
// EPI 0: sigmoid(acc + extra[col]) | EPI 1: plain | EPI 2: APPNP blend
// grid: (ceil(M/128), 2, batches); 256 threads = 8 warps, warp tile 64x32
// ---------------------------------------------------------------------------
template <int EPI>
__global__ void __launch_bounds__(256, 2)
tc_gemm(const float* __restrict__ A, long strideA,
        const float* __restrict__ Bm, long strideB,
        const float* __restrict__ extra, long strideE,
        float* __restrict__ C, long strideC,
        int M, int K, int S)
{
    extern __shared__ float smem[];
    const int t = threadIdx.x;
    const int m0 = blockIdx.x * 128;
    const int col0 = blockIdx.y * 128;
    A += (size_t)blockIdx.z * strideA;
    Bm += (size_t)blockIdx.z * strideB;
    extra += (size_t)blockIdx.z * strideE;
    C += (size_t)blockIdx.z * strideC;

    const int w = t >> 5, lane = t & 31;
    const int g = lane >> 2, tg = lane & 3;
    const int warpM = (w & 1) * 64;          // 2 warps along M
    const int warpN = (w >> 1) * 32;         // 4 warps along N

    float acc[4][4][4];
    #pragma unroll
    for (int i = 0; i < 4; i++)
        #pragma unroll
        for (int j = 0; j < 4; j++)
            #pragma unroll
            for (int q = 0; q < 4; q++) acc[i][j][q] = 0.0f;

    auto stage = [&](int s, int p) {
        const int k0 = s * 32;
        float* As = smem + p * 2 * STAGE_FLOATS;
        float* Bs = As + STAGE_FLOATS;
        #pragma unroll
        for (int i = 0; i < 4; i++) {
            int idx = t + i * 256;
            int row = idx >> 3, q = idx & 7;
            int gr = m0 + row, k = k0 + q * 4;
            float4 v = make_float4(0.f, 0.f, 0.f, 0.f);
            if (gr < M && k < K) v = *(const float4*)(A + (size_t)gr * K + k);
            float4 c4;
            c4.x = __uint_as_float(f2tf(v.x));
            c4.y = __uint_as_float(f2tf(v.y));
            c4.z = __uint_as_float(f2tf(v.z));
            c4.w = __uint_as_float(f2tf(v.w));
            *(float4*)(As + row * TSTRIDE + q * 4) = c4;
        }
        #pragma unroll
        for (int i = 0; i < 4; i++) {
            int idx = t + i * 256;
            int row = idx >> 3, q = idx & 7;
            int k = k0 + q * 4;
            float4 v = make_float4(0.f, 0.f, 0.f, 0.f);
            if (k < K) v = *(const float4*)(Bm + (size_t)(col0 + row) * K + k);
            float4 c4;
            c4.x = __uint_as_float(f2tf(v.x));
            c4.y = __uint_as_float(f2tf(v.y));
            c4.z = __uint_as_float(f2tf(v.z));
            c4.w = __uint_as_float(f2tf(v.w));
            *(float4*)(Bs + row * TSTRIDE + q * 4) = c4;
        }
    };

    auto compute = [&](int p) {
        const uint32_t* As = (const uint32_t*)(smem + p * 2 * STAGE_FLOATS);
        const uint32_t* Bs = As + STAGE_FLOATS;
        #pragma unroll
        for (int ks = 0; ks < 4; ks++) {
            const int kb = ks * 8;
            uint32_t af[4][4];
            #pragma unroll
            for (int mt = 0; mt < 4; mt++) {
                const int r = warpM + mt * 16;
                af[mt][0] = As[(r + g) * TSTRIDE + kb + tg];
                af[mt][1] = As[(r + g + 8) * TSTRIDE + kb + tg];
                af[mt][2] = As[(r + g) * TSTRIDE + kb + tg + 4];
                af[mt][3] = As[(r + g + 8) * TSTRIDE + kb + tg + 4];
            }
            #pragma unroll
            for (int nt = 0; nt < 4; nt++) {
                const int c = warpN + nt * 8 + g;
                uint32_t b0 = Bs[c * TSTRIDE + kb + tg];
                uint32_t b1 = Bs[c * TSTRIDE + kb + tg + 4];
                #pragma unroll
                for (int mt = 0; mt < 4; mt++)
                    mma_tf32(acc[mt][nt], af[mt], b0, b1);
            }
        }
    };

    stage(0, 0);
    __syncthreads();
    for (int s = 0; s < S; s++) {
        const int p = s & 1;
        if (s + 1 < S) stage(s + 1, p ^ 1);
        compute(p);
        __syncthreads();
    }

    // Epilogue
    #pragma unroll
    for (int mt = 0; mt < 4; mt++) {
        #pragma unroll
        for (int half = 0; half < 2; half++) {
            int r = m0 + warpM + mt * 16 + g + half * 8;
            if (r >= M) continue;
            #pragma unroll
            for (int nt = 0; nt < 4; nt++) {
                int cc = col0 + warpN + nt * 8 + tg * 2;
                float v0 = acc[mt][nt][half * 2 + 0];
                float v1 = acc[mt][nt][half * 2 + 1];
                float2 o;
                if (EPI == 0) {
                    float2 bb = *(const float2*)(extra + cc);
                    o.x = 1.0f / (1.0f + __expf(-(v0 + bb.x)));
                    o.y = 1.0f / (1.0f + __expf(-(v1 + bb.y)));
                } else if (EPI == 2) {
                    float2 e = *(const float2*)(extra + (size_t)r * 256 + cc);
                    o.x = (1.0f - ALPHA_C) * v0 + ALPHA_C * e.x;
                    o.y = (1.0f - ALPHA_C) * v1 + ALPHA_C * e.y;
                } else {
                    o.x = v0; o.y = v1;
                }
                *(float2*)(C + (size_t)r * 256 + cc) = o;
            }
        }
    }
}

// ---------------------------------------------------------------------------
// Tiled transpose: in [R][C] -> out [C][R], batched via blockIdx.z
// ---------------------------------------------------------------------------
__global__ void k_transpose(const float* __restrict__ in, float* __restrict__ out,
                            int R, int C, long sIn, long sOut)
{
    __shared__ float tile[32][33];
    in += (size_t)blockIdx.z * sIn;
    out += (size_t)blockIdx.z * sOut;
    int c = blockIdx.x * 32 + threadIdx.x;
    int r = blockIdx.y * 32 + threadIdx.y;
    #pragma unroll
    for (int i = 0; i < 4; i++) {
        int rr = r + i * 8;
        if (rr < R && c < C) tile[threadIdx.y + i * 8][threadIdx.x] = in[(size_t)rr * C + c];
    }
    __syncthreads();
    int c2 = blockIdx.y * 32 + threadIdx.x;
    int r2 = blockIdx.x * 32 + threadIdx.y;
    #pragma unroll
    for (int i = 0; i < 4; i++) {
        int rr = r2 + i * 8;
        if (rr < C && c2 < R) out[(size_t)rr * R + c2] = tile[threadIdx.x][threadIdx.y + i * 8];
    }
}

// ---------------------------------------------------------------------------
// Mask bitmap: bit set where (a[n][m]==0 && m!=n)
// ---------------------------------------------------------------------------
__global__ void k_mask(const float* __restrict__ a, unsigned* __restrict__ mb)
{
    int i = blockIdx.x * blockDim.x + threadIdx.x;
    if (i >= Nn * 13) return;
    int n = i / 13, w = i - n * 13;
    unsigned bits = 0;
    #pragma unroll
    for (int j = 0; j < 32; j++) {
        int m = w * 32 + j;
        if (m < Nn && m != n && a[(size_t)n * Nn + m] == 0.0f) bits |= 1u << j;
    }
    mb[i] = bits;
}

// ---------------------------------------------------------------------------
// s/ng projections (one warp per (b,n))
// ---------------------------------------------------------------------------
__global__ void k_proj(const float* __restrict__ xp,
                       const float* __restrict__ ak_self,
                       const float* __restrict__ ak_neigh,
                       float* __restrict__ sT, float* __restrict__ ngT)
{
    int gw = (blockIdx.x * blockDim.x + threadIdx.x) >> 5;
    int lane = threadIdx.x & 31;
    if (gw >= BN) return;
    int b = gw / Nn, n = gw - b * Nn;
    const float* xr = xp + (size_t)gw * HO;
    #pragma unroll
    for (int h = 0; h < Hh; h++) {
        float v0 = xr[h * 64 + lane];
        float v1 = xr[h * 64 + 32 + lane];
        float ss = v0 * ak_self[lane * Hh + h] + v1 * ak_self[(lane + 32) * Hh + h];
        float ng = v0 * ak_neigh[lane * Hh + h] + v1 * ak_neigh[(lane + 32) * Hh + h];
        #pragma unroll
        for (int off = 16; off > 0; off >>= 1) {
            ss += __shfl_down_sync(0xffffffffu, ss, off);
            ng += __shfl_down_sync(0xffffffffu, ng, off);
        }
        if (lane == 0) {
            sT[(b * Hh + h) * Nn + n] = ss;
            ngT[(b * Hh + h) * Nn + n] = ng;
        }
    }
}

// ---------------------------------------------------------------------------
// Softmax stats (bitmask; masked entries excluded exactly)
// ---------------------------------------------------------------------------
__global__ void k_stats(const unsigned* __restrict__ mb,
                        const float* __restrict__ sT,
                        const float* __restrict__ ngT,
                        float* __restrict__ mx, float* __restrict__ isum)
{
    const int n = blockIdx.x, b = blockIdx.y;
    const int h = threadIdx.x >> 5, lane = threadIdx.x & 31;
    const int bh = b * Hh + h;
    const float sv = sT[bh * Nn + n];
    const float* ngr = ngT + (size_t)bh * Nn;

    float lv[13];
    float m = -3.0e38f;
    #pragma unroll
    for (int it = 0; it < 13; it++) {
        int mm = lane + it * 32;
        unsigned wd = mb[n * 13 + it];
        float l = -3.0e38f;
        if (mm < Nn && !((wd >> lane) & 1u)) {
            float l0 = sv + ngr[mm];
            l = (l0 > 0.0f) ? l0 : LEAKY_C * l0;
        }
        lv[it] = l;
        m = fmaxf(m, l);
    }
    #pragma unroll
    for (int off = 16; off > 0; off >>= 1)
        m = fmaxf(m, __shfl_xor_sync(0xffffffffu, m, off));

    float s = 0.0f;
    #pragma unroll
    for (int it = 0; it < 13; it++) {
        if (lv[it] > -1.0e38f) s += __expf(lv[it] - m);
    }
    #pragma unroll
    for (int off = 16; off > 0; off >>= 1)
        s += __shfl_xor_sync(0xffffffffu, s, off);

    if (lane == 0) {
        mx[bh * Nn + n] = m;
        isum[bh * Nn + n] = 1.0f / s;
    }
}

// ---------------------------------------------------------------------------
// AV: out[b,n,h,:] = sum_m P(b,h,n,m) * xp[b,m,h,:]  (+bias, ELU)
// ---------------------------------------------------------------------------
__global__ void k_av(const float* __restrict__ xp,
                     const unsigned* __restrict__ mb,
                     const float* __restrict__ sT,
                     const float* __restrict__ ngT,
                     const float* __restrict__ mx,
                     const float* __restrict__ isum,
                     const float* __restrict__ bias,
                     float* __restrict__ out)
{
    const int n0 = blockIdx.x * 64;
    const int h = blockIdx.y, b = blockIdx.z;
    const int bh = b * Hh + h;
    __shared__ float xpS[32 * 64];
    __shared__ float PsT[32 * 68];
    __shared__ float sSh[64], mSh[64], iSh[64], ngS[32];
    const int t = threadIdx.x;

    if (t < 64) {
        int n = n0 + t;
        bool v = (n < Nn);
        sSh[t] = v ? sT[bh * Nn + n] : 0.0f;
        mSh[t] = v ? mx[bh * Nn + n] : 0.0f;
        iSh[t] = v ? isum[bh * Nn + n] : 0.0f;
    }
    __syncthreads();

    const int tx = t & 15;
    const int ty = t >> 4;
    float acc[4][4] = {};

    for (int m0 = 0; m0 < Nn; m0 += 32) {
        if (t < 32) {
            int gm = m0 + t;
            ngS[t] = (gm < Nn) ? ngT[(size_t)bh * Nn + gm] : 0.0f;
        }
        #pragma unroll
        for (int i = 0; i < 2; i++) {
            int idx = t + i * 256;
            int mm = idx >> 4, q = idx & 15;
            int gm = m0 + mm;
            float4 v = make_float4(0.f, 0.f, 0.f, 0.f);
            if (gm < Nn)
                v = *(const float4*)(xp + ((size_t)(b * Nn + gm)) * 256 + h * 64 + q * 4);
            *(float4*)&xpS[mm * 64 + q * 4] = v;
        }
        __syncthreads();
        #pragma unroll
        for (int i = 0; i < 8; i++) {
            int e = t + i * 256;
            int mi = e >> 6, r = e & 63;
            int gm = m0 + mi, gn = n0 + r;
            float p = 0.0f;
            if (gm < Nn && gn < Nn) {
                bool msk = (mb[gn * 13 + (gm >> 5)] >> (gm & 31)) & 1u;
                if (!msk) {
                    float l0 = sSh[r] + ngS[mi];
                    float l = (l0 > 0.0f) ? l0 : LEAKY_C * l0;
                    p = __expf(l - mSh[r]) * iSh[r];
                }
            }
            PsT[mi * 68 + r] = p;
        }
        __syncthreads();
        #pragma unroll
        for (int mm = 0; mm < 32; mm++) {
            float4 pr = *(const float4*)&PsT[mm * 68 + ty * 4];
            float4 xv = *(const float4*)&xpS[mm * 64 + tx * 4];
            acc[0][0] += pr.x * xv.x; acc[0][1] += pr.x * xv.y;
            acc[0][2] += pr.x * xv.z; acc[0][3] += pr.x * xv.w;
            acc[1][0] += pr.y * xv.x; acc[1][1] += pr.y * xv.y;
            acc[1][2] += pr.y * xv.z; acc[1][3] += pr.y * xv.w;
            acc[2][0] += pr.z * xv.x; acc[2][1] += pr.z * xv.y;
            acc[2][2] += pr.z * xv.z; acc[2][3] += pr.z * xv.w;
            acc[3][0] += pr.w * xv.x; acc[3][1] += pr.w * xv.y;
            acc[3][2] += pr.w * xv.z; acc[3][3] += pr.w * xv.w;
        }
        __syncthreads();
    }

    #pragma unroll
    for (int i = 0; i < 4; i++) {
        int n = n0 + ty * 4 + i;
        if (n >= Nn) continue;
        int c = h * 64 + tx * 4;
        float4 bb = *(const float4*)(bias + c);
        float4 v;
        v.x = acc[i][0] + bb.x; v.y = acc[i][1] + bb.y;
        v.z = acc[i][2] + bb.z; v.w = acc[i][3] + bb.w;
        v.x = (v.x > 0.0f) ? v.x : expm1f(v.x);
        v.y = (v.y > 0.0f) ? v.y : expm1f(v.y);
        v.z = (v.z > 0.0f) ? v.z : expm1f(v.z);
        v.w = (v.w > 0.0f) ? v.w : expm1f(v.w);
        *(float4*)(out + ((size_t)(b * Nn + n)) * 256 + c) = v;
    }
}

// ---------------------------------------------------------------------------
extern "C" void kernel_launch(void* const* d_in, const int* in_sizes, int n_in,
                              void* d_out, int out_size)
{
    const float* x        = (const float*)d_in[0];
    const float* a        = (const float*)d_in[1];
    const float* w_mlp    = (const float*)d_in[2];
    const float* b_mlp    = (const float*)d_in[3];
    const float* kern     = (const float*)d_in[4];
    const float* ak_self  = (const float*)d_in[5];
    const float* ak_neigh = (const float*)d_in[6];
    const float* bias     = (const float*)d_in[7];
    float* out = (float*)d_out;

    float *p_mlp, *p_mlpT, *p_z, *p_xp, *p_wT, *p_kT, *p_sT, *p_ngT, *p_mx, *p_isum;
    unsigned* p_mbits;
    cudaGetSymbolAddress((void**)&p_mlp, g_mlp);
    cudaGetSymbolAddress((void**)&p_mlpT, g_mlpT);
    cudaGetSymbolAddress((void**)&p_z, g_z);
    cudaGetSymbolAddress((void**)&p_xp, g_xp);
    cudaGetSymbolAddress((void**)&p_wT, g_wT);
    cudaGetSymbolAddress((void**)&p_kT, g_kT);
    cudaGetSymbolAddress((void**)&p_sT, g_sT);
    cudaGetSymbolAddress((void**)&p_ngT, g_ngT);
    cudaGetSymbolAddress((void**)&p_mx, g_mx);
    cudaGetSymbolAddress((void**)&p_isum, g_isum);
    cudaGetSymbolAddress((void**)&p_mbits, g_mbits);

    cudaFuncSetAttribute(tc_gemm<0>, cudaFuncAttributeMaxDynamicSharedMemorySize, SMEM_TC);
    cudaFuncSetAttribute(tc_gemm<1>, cudaFuncAttributeMaxDynamicSharedMemorySize, SMEM_TC);
    cudaFuncSetAttribute(tc_gemm<2>, cudaFuncAttributeMaxDynamicSharedMemorySize, SMEM_TC);

    k_transpose<<<dim3(8, 8, 1), dim3(32, 8)>>>(w_mlp, p_wT, 256, 256, 0, 0);
    k_transpose<<<dim3(8, 8, 1), dim3(32, 8)>>>(kern, p_kT, 256, 256, 0, 0);
    k_mask<<<(Nn * 13 + 127) / 128, 128>>>(a, p_mbits);

    // 1. mlp = sigmoid(x @ w_mlp + b)      [tf32 mma]
    tc_gemm<0><<<dim3((BN + 127) / 128, 2, 1), 256, SMEM_TC>>>(
        x, 0, p_wT, 0, b_mlp, 0, p_mlp, 0, BN, 256, 8);
    // 2. mlpT per batch
    k_transpose<<<dim3(8, 13, Bb), dim3(32, 8)>>>(p_mlp, p_mlpT, Nn, 256,
                                                  (long)Nn * 256, (long)Nn * 256);
    // 3. z = 0.8 * adj @ mlp + 0.2 * mlp   [tf32 mma]
    tc_gemm<2><<<dim3(4, 2, Bb), 256, SMEM_TC>>>(
        a, 0, p_mlpT, (long)Nn * 256, p_mlp, (long)Nn * 256, p_z, (long)Nn * 256,
        Nn, Nn, 13);
    // 4. xp = z @ kernel                   [tf32 mma]
    tc_gemm<1><<<dim3((BN + 127) / 128, 2, 1), 256, SMEM_TC>>>(
        p_z, 0, p_kT, 0, nullptr, 0, p_xp, 0, BN, 256, 8);
    // 5. s / ng projections
    k_proj<<<(BN * 32 + 255) / 256, 256>>>(p_xp, ak_self, ak_neigh, p_sT, p_ngT);
    // 6. softmax stats
    k_stats<<<dim3(Nn, Bb), 128>>>(p_mbits, p_sT, p_ngT, p_mx, p_isum);
    // 7. AV + bias + ELU
    k_av<<<dim3((Nn + 63) / 64, Hh, Bb), 256>>>(p_xp, p_mbits, p_sT, p_ngT,
                                                p_mx, p_isum, bias, out);
}

// round 5
// speedup vs baseline: 2.9093x; 1.8175x over previous
#include <cuda_runtime.h>
#include <cuda_fp16.h>
#include <cstdint>

// Problem constants
constexpr int Bb = 108;
constexpr int Nn = 392;
constexpr int Hh = 4;
constexpr int HO = 256;
constexpr int BN = Bb * Nn;     // 42336
constexpr int BH = Bb * Hh;     // 432

#define ALPHA_C   0.2f
#define LEAKY_C   0.2f

// Scratch (allocation-free: __device__ globals)
__device__ float g_mlp[BN * HO];
__device__ float g_mlpT[BN * HO];
__device__ float g_z[BN * HO];
__device__ float g_xp[BN * HO];
__device__ float g_wT[256 * 256];
__device__ float g_kT[256 * 256];
__device__ float g_sT[BH * Nn];
__device__ float g_ngT[BH * Nn];
__device__ float g_isum[BH * Nn];
__device__ unsigned g_mbits[Nn * 13];
__device__ __half g_E[(size_t)BH * Nn * Nn];       // exp(l - rowmax), fp16
__device__ __half g_xpHT[(size_t)BH * 64 * Nn];    // xp transposed per (b,h): [o][m]

// ---------------------------------------------------------------------------
// fp16 mma helper: m16n8k16 f32.f16.f16.f32
// ---------------------------------------------------------------------------
__device__ __forceinline__ void mma_f16(float* c, const uint32_t* a,
                                        uint32_t b0, uint32_t b1) {
    asm volatile(
        "mma.sync.aligned.m16n8k16.row.col.f32.f16.f16.f32 "
        "{%0,%1,%2,%3}, {%4,%5,%6,%7}, {%8,%9}, {%0,%1,%2,%3};"
        : "+f"(c[0]), "+f"(c[1]), "+f"(c[2]), "+f"(c[3])
        : "r"(a[0]), "r"(a[1]), "r"(a[2]), "r"(a[3]), "r"(b0), "r"(b1));
}

// smem row stride: 40 halves (=20 u32, 80B) -> conflict-free 32-bit frag reads
constexpr int STH = 40;          // halves per row
constexpr int STU = 20;          // u32 per row

// ---------------------------------------------------------------------------
// fp16 GEMM: C[M,256] = A[M,K] @ B^T, A fp32 [M,K], B fp32 [256,K] k-major.
// EPI 0: sigmoid(acc+extra[col]) | 1: plain | 2: APPNP blend
// 256 thr = 8 warps, CTA 128x128, warp 64x32, ktile 32 double-buffered.
// ---------------------------------------------------------------------------
template <int EPI>
__global__ void __launch_bounds__(256, 2)
tc_gemm(const float* __restrict__ A, long strideA,
        const float* __restrict__ Bm, long strideB,
        const float* __restrict__ extra, long strideE,
        float* __restrict__ C, long strideC,
        int M, int K, int S)
{
    extern __shared__ uint32_t smem[];          // u32 units
    const int t = threadIdx.x;
    const int m0 = blockIdx.x * 128;
    const int col0 = blockIdx.y * 128;
    A += (size_t)blockIdx.z * strideA;
    Bm += (size_t)blockIdx.z * strideB;
    extra += (size_t)blockIdx.z * strideE;
    C += (size_t)blockIdx.z * strideC;

    const int w = t >> 5, lane = t & 31;
    const int g = lane >> 2, tg = lane & 3;
    const int warpM = (w & 1) * 64;
    const int warpN = (w >> 1) * 32;

    constexpr int STAGE_U = 2 * 128 * STU;      // A(128)+B(128) rows per stage

    float acc[4][4][4];
    #pragma unroll
    for (int i = 0; i < 4; i++)
        #pragma unroll
        for (int j = 0; j < 4; j++)
            #pragma unroll
            for (int q = 0; q < 4; q++) acc[i][j][q] = 0.0f;

    auto stage = [&](int s, int p) {
        const int k0 = s * 32;
        uint32_t* As = smem + p * STAGE_U;
        uint32_t* Bs = As + 128 * STU;
        #pragma unroll
        for (int i = 0; i < 4; i++) {
            int idx = t + i * 256;
            int row = idx >> 3, q = idx & 7;
            int gr = m0 + row, k = k0 + q * 4;
            float4 v = make_float4(0.f, 0.f, 0.f, 0.f);
            if (gr < M && k < K) v = *(const float4*)(A + (size_t)gr * K + k);
            __half2 p0 = __floats2half2_rn(v.x, v.y);
            __half2 p1 = __floats2half2_rn(v.z, v.w);
            uint32_t* d = As + row * STU + q * 2;
            d[0] = *(uint32_t*)&p0; d[1] = *(uint32_t*)&p1;
        }
        #pragma unroll
        for (int i = 0; i < 4; i++) {
            int idx = t + i * 256;
            int row = idx >> 3, q = idx & 7;
            int k = k0 + q * 4;
            float4 v = make_float4(0.f, 0.f, 0.f, 0.f);
            if (k < K) v = *(const float4*)(Bm + (size_t)(col0 + row) * K + k);
            __half2 p0 = __floats2half2_rn(v.x, v.y);
            __half2 p1 = __floats2half2_rn(v.z, v.w);
            uint32_t* d = Bs + row * STU + q * 2;
            d[0] = *(uint32_t*)&p0; d[1] = *(uint32_t*)&p1;
        }
    };

    auto compute = [&](int p) {
        const uint32_t* As = smem + p * STAGE_U;
        const uint32_t* Bs = As + 128 * STU;
        #pragma unroll
        for (int ks = 0; ks < 2; ks++) {
            const int kb = ks * 8;              // u32 offset (16 halves)
            uint32_t af[4][4];
            #pragma unroll
            for (int mt = 0; mt < 4; mt++) {
                const int r = warpM + mt * 16;
                af[mt][0] = As[(r + g) * STU + kb + tg];
                af[mt][1] = As[(r + g + 8) * STU + kb + tg];
                af[mt][2] = As[(r + g) * STU + kb + tg + 4];
                af[mt][3] = As[(r + g + 8) * STU + kb + tg + 4];
            }
            #pragma unroll
            for (int nt = 0; nt < 4; nt++) {
                const int c = warpN + nt * 8 + g;
                uint32_t b0 = Bs[c * STU + kb + tg];
                uint32_t b1 = Bs[c * STU + kb + tg + 4];
                #pragma unroll
                for (int mt = 0; mt < 4; mt++)
                    mma_f16(acc[mt][nt], af[mt], b0, b1);
            }
        }
    };

    stage(0, 0);
    __syncthreads();
    for (int s = 0; s < S; s++) {
        const int p = s & 1;
        if (s + 1 < S) stage(s + 1, p ^ 1);
        compute(p);
        __syncthreads();
    }

    #pragma unroll
    for (int mt = 0; mt < 4; mt++) {
        #pragma unroll
        for (int half = 0; half < 2; half++) {
            int r = m0 + warpM + mt * 16 + g + half * 8;
            if (r >= M) continue;
            #pragma unroll
            for (int nt = 0; nt < 4; nt++) {
                int cc = col0 + warpN + nt * 8 + tg * 2;
                float v0 = acc[mt][nt][half * 2 + 0];
                float v1 = acc[mt][nt][half * 2 + 1];
                float2 o;
                if (EPI == 0) {
                    float2 bb = *(const float2*)(extra + cc);
                    o.x = 1.0f / (1.0f + __expf(-(v0 + bb.x)));
                    o.y = 1.0f / (1.0f + __expf(-(v1 + bb.y)));
                } else if (EPI == 2) {
                    float2 e = *(const float2*)(extra + (size_t)r * 256 + cc);
                    o.x = (1.0f - ALPHA_C) * v0 + ALPHA_C * e.x;
                    o.y = (1.0f - ALPHA_C) * v1 + ALPHA_C * e.y;
                } else {
                    o.x = v0; o.y = v1;
                }
                *(float2*)(C + (size_t)r * 256 + cc) = o;
            }
        }
    }
}
constexpr unsigned SMEM_TC = 2u * 2u * 128u * STU * 4u;    // 40960 B

// ---------------------------------------------------------------------------
// AV GEMM (fp16): C[392x64] = E[392x392] @ xpHT^T per (b,h); epilogue:
// scale row by isum, add bias, ELU. CTA 128x64, 8 warps 32x32, ktile 32.
// ---------------------------------------------------------------------------
__global__ void __launch_bounds__(256, 2)
tc_av(const __half* __restrict__ E, const __half* __restrict__ xpHT,
      const float* __restrict__ isum, const float* __restrict__ bias,
      float* __restrict__ out)
{
    extern __shared__ uint32_t smem[];
    const int t = threadIdx.x;
    const int m0 = blockIdx.x * 128;
    const int bh = blockIdx.z;
    const int b = bh >> 2, h = bh & 3;

    const int w = t >> 5, lane = t & 31;
    const int g = lane >> 2, tg = lane & 3;
    const int warpM = (w & 3) * 32;
    const int warpN = (w >> 2) * 32;

    constexpr int STAGE_U = (128 + 64) * STU;

    float acc[2][4][4];
    #pragma unroll
    for (int i = 0; i < 2; i++)
        #pragma unroll
        for (int j = 0; j < 4; j++)
            #pragma unroll
            for (int q = 0; q < 4; q++) acc[i][j][q] = 0.0f;

    const __half* Eb = E + (size_t)bh * Nn * Nn;
    const __half* Xb = xpHT + (size_t)bh * 64 * Nn;

    auto stage = [&](int s, int p) {
        const int k0 = s * 32;
        uint32_t* As = smem + p * STAGE_U;
        uint32_t* Bs = As + 128 * STU;
        // E rows: 128 rows x 4 chunks of 8 halves = 512 chunks, 2 iters
        #pragma unroll
        for (int i = 0; i < 2; i++) {
            int idx = t + i * 256;
            int row = idx >> 2, q = idx & 3;
            int gr = m0 + row, k = k0 + q * 8;
            uint4 v = make_uint4(0u, 0u, 0u, 0u);
            if (gr < Nn && k < Nn)
                v = *(const uint4*)(Eb + (size_t)gr * Nn + k);
            *(uint4*)(As + row * STU + q * 4) = v;
        }
        // xpHT rows: 64 rows x 4 chunks = 256 chunks, 1 iter
        {
            int row = t >> 2, q = t & 3;
            int k = k0 + q * 8;
            uint4 v = make_uint4(0u, 0u, 0u, 0u);
            if (k < Nn)
                v = *(const uint4*)(Xb + (size_t)row * Nn + k);
            *(uint4*)(Bs + row * STU + q * 4) = v;
        }
    };

    auto compute = [&](int p) {
        const uint32_t* As = smem + p * STAGE_U;
        const uint32_t* Bs = As + 128 * STU;
        #pragma unroll
        for (int ks = 0; ks < 2; ks++) {
            const int kb = ks * 8;
            uint32_t af[2][4];
            #pragma unroll
            for (int mt = 0; mt < 2; mt++) {
                const int r = warpM + mt * 16;
                af[mt][0] = As[(r + g) * STU + kb + tg];
                af[mt][1] = As[(r + g + 8) * STU + kb + tg];
                af[mt][2] = As[(r + g) * STU + kb + tg + 4];
                af[mt][3] = As[(r + g + 8) * STU + kb + tg + 4];
            }
            #pragma unroll
            for (int nt = 0; nt < 4; nt++) {
                const int c = warpN + nt * 8 + g;
                uint32_t b0 = Bs[c * STU + kb + tg];
                uint32_t b1 = Bs[c * STU + kb + tg + 4];
                #pragma unroll
                for (int mt = 0; mt < 2; mt++)
                    mma_f16(acc[mt][nt], af[mt], b0, b1);
            }
        }
    };

    constexpr int S = (Nn + 31) / 32;    // 13
    stage(0, 0);
    __syncthreads();
    for (int s = 0; s < S; s++) {
        const int p = s & 1;
        if (s + 1 < S) stage(s + 1, p ^ 1);
        compute(p);
        __syncthreads();
    }

    #pragma unroll
    for (int mt = 0; mt < 2; mt++) {
        #pragma unroll
        for (int half = 0; half < 2; half++) {
            int r = m0 + warpM + mt * 16 + g + half * 8;
            if (r >= Nn) continue;
            float sc = isum[bh * Nn + r];
            #pragma unroll
            for (int nt = 0; nt < 4; nt++) {
                int cc = warpN + nt * 8 + tg * 2;
                float2 bb = *(const float2*)(bias + h * 64 + cc);
                float v0 = acc[mt][nt][half * 2 + 0] * sc + bb.x;
                float v1 = acc[mt][nt][half * 2 + 1] * sc + bb.y;
                v0 = (v0 > 0.0f) ? v0 : expm1f(v0);
                v1 = (v1 > 0.0f) ? v1 : expm1f(v1);
                *(float2*)(out + ((size_t)(b * Nn + r)) * 256 + h * 64 + cc) =
                    make_float2(v0, v1);
            }
        }
    }
}
constexpr unsigned SMEM_AV = 2u * (128u + 64u) * STU * 4u;  // 30720 B

// ---------------------------------------------------------------------------
// Tiled transpose fp32: in [R][C] -> out [C][R], batched via blockIdx.z
// ---------------------------------------------------------------------------
__global__ void k_transpose(const float* __restrict__ in, float* __restrict__ out,
                            int R, int C, long sIn, long sOut)
{
    __shared__ float tile[32][33];
    in += (size_t)blockIdx.z * sIn;
    out += (size_t)blockIdx.z * sOut;
    int c = blockIdx.x * 32 + threadIdx.x;
    int r = blockIdx.y * 32 + threadIdx.y;
    #pragma unroll
    for (int i = 0; i < 4; i++) {
        int rr = r + i * 8;
        if (rr < R && c < C) tile[threadIdx.y + i * 8][threadIdx.x] = in[(size_t)rr * C + c];
    }
    __syncthreads();
    int c2 = blockIdx.y * 32 + threadIdx.x;
    int r2 = blockIdx.x * 32 + threadIdx.y;
    #pragma unroll
    for (int i = 0; i < 4; i++) {
        int rr = r2 + i * 8;
        if (rr < C && c2 < R) out[(size_t)rr * R + c2] = tile[threadIdx.x][threadIdx.y + i * 8];
    }
}

// ---------------------------------------------------------------------------
// xp [b,n,256] fp32 -> xpHT [(b,h), o, n] fp16
// grid (13 nTiles, 2 oTiles, 432), block (32,8)
// ---------------------------------------------------------------------------
__global__ void k_xpT(const float* __restrict__ xp, __half* __restrict__ xpHT)
{
    __shared__ float tile[32][33];
    const int bh = blockIdx.z;
    const int b = bh >> 2, h = bh & 3;
    int o = blockIdx.y * 32 + threadIdx.x;
    int n = blockIdx.x * 32 + threadIdx.y;
    #pragma unroll
    for (int i = 0; i < 4; i++) {
        int nn = n + i * 8;
        if (nn < Nn)
            tile[threadIdx.y + i * 8][threadIdx.x] =
                xp[((size_t)(b * Nn + nn)) * 256 + h * 64 + o];
    }
    __syncthreads();
    int n2 = blockIdx.x * 32 + threadIdx.x;
    int o2 = blockIdx.y * 32 + threadIdx.y;
    #pragma unroll
    for (int i = 0; i < 4; i++) {
        int oo = o2 + i * 8;
        if (n2 < Nn)
            xpHT[((size_t)bh * 64 + oo) * Nn + n2] =
                __float2half_rn(tile[threadIdx.x][threadIdx.y + i * 8]);
    }
}

// ---------------------------------------------------------------------------
// Mask bitmap
// ---------------------------------------------------------------------------
__global__ void k_mask(const float* __restrict__ a, unsigned* __restrict__ mb)
{
    int i = blockIdx.x * blockDim.x + threadIdx.x;
    if (i >= Nn * 13) return;
    int n = i / 13, w = i - n * 13;
    unsigned bits = 0;
    #pragma unroll
    for (int j = 0; j < 32; j++) {
        int m = w * 32 + j;
        if (m < Nn && m != n && a[(size_t)n * Nn + m] == 0.0f) bits |= 1u << j;
    }
    mb[i] = bits;
}

// ---------------------------------------------------------------------------
// s/ng projections (one warp per (b,n))
// ---------------------------------------------------------------------------
__global__ void k_proj(const float* __restrict__ xp,
                       const float* __restrict__ ak_self,
                       const float* __restrict__ ak_neigh,
                       float* __restrict__ sT, float* __restrict__ ngT)
{
    int gw = (blockIdx.x * blockDim.x + threadIdx.x) >> 5;
    int lane = threadIdx.x & 31;
    if (gw >= BN) return;
    int b = gw / Nn, n = gw - b * Nn;
    const float* xr = xp + (size_t)gw * HO;
    #pragma unroll
    for (int h = 0; h < Hh; h++) {
        float v0 = xr[h * 64 + lane];
        float v1 = xr[h * 64 + 32 + lane];
        float ss = v0 * ak_self[lane * Hh + h] + v1 * ak_self[(lane + 32) * Hh + h];
        float ng = v0 * ak_neigh[lane * Hh + h] + v1 * ak_neigh[(lane + 32) * Hh + h];
        #pragma unroll
        for (int off = 16; off > 0; off >>= 1) {
            ss += __shfl_down_sync(0xffffffffu, ss, off);
            ng += __shfl_down_sync(0xffffffffu, ng, off);
        }
        if (lane == 0) {
            sT[(b * Hh + h) * Nn + n] = ss;
            ngT[(b * Hh + h) * Nn + n] = ng;
        }
    }
}

// ---------------------------------------------------------------------------
// Stats + E write: per (b,h,n) row, compute rowmax, e=exp(l-m) (fp16), isum.
// grid (392, 108), block 128 (4 warps = 4 heads)
// ---------------------------------------------------------------------------
__global__ void k_stats_e(const unsigned* __restrict__ mb,
                          const float* __restrict__ sT,
                          const float* __restrict__ ngT,
                          __half* __restrict__ E,
                          float* __restrict__ isum)
{
    const int n = blockIdx.x, b = blockIdx.y;
    const int h = threadIdx.x >> 5, lane = threadIdx.x & 31;
    const int bh = b * Hh + h;
    const float sv = sT[bh * Nn + n];
    const float* ngr = ngT + (size_t)bh * Nn;
    __half* Erow = E + ((size_t)bh * Nn + n) * Nn;

    float lv[13];
    float m = -3.0e38f;
    #pragma unroll
    for (int it = 0; it < 13; it++) {
        int mm = lane + it * 32;
        unsigned wd = mb[n * 13 + it];
        float l = -3.0e38f;
        if (mm < Nn && !((wd >> lane) & 1u)) {
            float l0 = sv + ngr[mm];
            l = (l0 > 0.0f) ? l0 : LEAKY_C * l0;
        }
        lv[it] = l;
        m = fmaxf(m, l);
    }
    #pragma unroll
    for (int off = 16; off > 0; off >>= 1)
        m = fmaxf(m, __shfl_xor_sync(0xffffffffu, m, off));

    float s = 0.0f;
    #pragma unroll
    for (int it = 0; it < 13; it++) {
        int mm = lane + it * 32;
        float e = 0.0f;
        if (lv[it] > -1.0e38f) e = __expf(lv[it] - m);
        s += e;
        if (mm < Nn) Erow[mm] = __float2half_rn(e);
    }
    #pragma unroll
    for (int off = 16; off > 0; off >>= 1)
        s += __shfl_xor_sync(0xffffffffu, s, off);

    if (lane == 0) isum[bh * Nn + n] = 1.0f / s;
}

// ---------------------------------------------------------------------------
extern "C" void kernel_launch(void* const* d_in, const int* in_sizes, int n_in,
                              void* d_out, int out_size)
{
    const float* x        = (const float*)d_in[0];
    const float* a        = (const float*)d_in[1];
    const float* w_mlp    = (const float*)d_in[2];
    const float* b_mlp    = (const float*)d_in[3];
    const float* kern     = (const float*)d_in[4];
    const float* ak_self  = (const float*)d_in[5];
    const float* ak_neigh = (const float*)d_in[6];
    const float* bias     = (const float*)d_in[7];
    float* out = (float*)d_out;

    float *p_mlp, *p_mlpT, *p_z, *p_xp, *p_wT, *p_kT, *p_sT, *p_ngT, *p_isum;
    unsigned* p_mbits;
    __half *p_E, *p_xpHT;
    cudaGetSymbolAddress((void**)&p_mlp, g_mlp);
    cudaGetSymbolAddress((void**)&p_mlpT, g_mlpT);
    cudaGetSymbolAddress((void**)&p_z, g_z);
    cudaGetSymbolAddress((void**)&p_xp, g_xp);
    cudaGetSymbolAddress((void**)&p_wT, g_wT);
    cudaGetSymbolAddress((void**)&p_kT, g_kT);
    cudaGetSymbolAddress((void**)&p_sT, g_sT);
    cudaGetSymbolAddress((void**)&p_ngT, g_ngT);
    cudaGetSymbolAddress((void**)&p_isum, g_isum);
    cudaGetSymbolAddress((void**)&p_mbits, g_mbits);
    cudaGetSymbolAddress((void**)&p_E, g_E);
    cudaGetSymbolAddress((void**)&p_xpHT, g_xpHT);

    k_transpose<<<dim3(8, 8, 1), dim3(32, 8)>>>(w_mlp, p_wT, 256, 256, 0, 0);
    k_transpose<<<dim3(8, 8, 1), dim3(32, 8)>>>(kern, p_kT, 256, 256, 0, 0);
    k_mask<<<(Nn * 13 + 127) / 128, 128>>>(a, p_mbits);

    // 1. mlp = sigmoid(x @ w_mlp + b)      [fp16 mma]
    tc_gemm<0><<<dim3((BN + 127) / 128, 2, 1), 256, SMEM_TC>>>(
        x, 0, p_wT, 0, b_mlp, 0, p_mlp, 0, BN, 256, 8);
    // 2. mlpT per batch
    k_transpose<<<dim3(8, 13, Bb), dim3(32, 8)>>>(p_mlp, p_mlpT, Nn, 256,
                                                  (long)Nn * 256, (long)Nn * 256);
    // 3. z = 0.8 * adj @ mlp + 0.2 * mlp   [fp16 mma]
    tc_gemm<2><<<dim3(4, 2, Bb), 256, SMEM_TC>>>(
        a, 0, p_mlpT, (long)Nn * 256, p_mlp, (long)Nn * 256, p_z, (long)Nn * 256,
        Nn, Nn, 13);
    // 4. xp = z @ kernel                   [fp16 mma]
    tc_gemm<1><<<dim3((BN + 127) / 128, 2, 1), 256, SMEM_TC>>>(
        p_z, 0, p_kT, 0, nullptr, 0, p_xp, 0, BN, 256, 8);
    // 5. s / ng projections
    k_proj<<<(BN * 32 + 255) / 256, 256>>>(p_xp, ak_self, ak_neigh, p_sT, p_ngT);
    // 6. xp -> fp16 transposed per (b,h)
    k_xpT<<<dim3(13, 2, BH), dim3(32, 8)>>>(p_xp, p_xpHT);
    // 7. stats + E (fp16)
    k_stats_e<<<dim3(Nn, Bb), 128>>>(p_mbits, p_sT, p_ngT, p_E, p_isum);
    // 8. AV gemm + scale + bias + ELU      [fp16 mma]
    tc_av<<<dim3((Nn + 127) / 128, 1, BH), 256, SMEM_AV>>>(
        p_E, p_xpHT, p_isum, bias, out);
}

// round 6
// speedup vs baseline: 3.4949x; 1.2013x over previous
#include <cuda_runtime.h>
#include <cuda_fp16.h>
#include <cstdint>

// Problem constants
constexpr int Bb = 108;
constexpr int Nn = 392;
constexpr int Hh = 4;
constexpr int HO = 256;
constexpr int BN = Bb * Nn;     // 42336
constexpr int BH = Bb * Hh;     // 432

#define ALPHA_C   0.2f
#define LEAKY_C   0.2f

// Scratch (allocation-free: __device__ globals)
__device__ __half g_xH[(size_t)BN * HO];
__device__ __half g_wTh[256 * 256];
__device__ __half g_kTh[256 * 256];
__device__ __half g_aH[Nn * Nn];
__device__ float  g_mlp[(size_t)BN * HO];
__device__ __half g_mlpTh[(size_t)BN * HO];
__device__ __half g_zH[(size_t)BN * HO];
__device__ float  g_xp[(size_t)BN * HO];
__device__ float  g_sT[BH * Nn];
__device__ float  g_ngT[BH * Nn];
__device__ float  g_isum[BH * Nn];
__device__ unsigned g_mbits[Nn * 13];
__device__ __half g_E[(size_t)BH * Nn * Nn];
__device__ __half g_xpHT[(size_t)BH * 64 * Nn];

// ---------------------------------------------------------------------------
// PTX helpers
// ---------------------------------------------------------------------------
__device__ __forceinline__ void mma_f16(float* c, const uint32_t* a,
                                        uint32_t b0, uint32_t b1) {
    asm volatile(
        "mma.sync.aligned.m16n8k16.row.col.f32.f16.f16.f32 "
        "{%0,%1,%2,%3}, {%4,%5,%6,%7}, {%8,%9}, {%0,%1,%2,%3};"
        : "+f"(c[0]), "+f"(c[1]), "+f"(c[2]), "+f"(c[3])
        : "r"(a[0]), "r"(a[1]), "r"(a[2]), "r"(a[3]), "r"(b0), "r"(b1));
}
__device__ __forceinline__ void cp16(uint32_t dst, const void* src, int sz) {
    asm volatile("cp.async.cg.shared.global [%0], [%1], 16, %2;"
                 :: "r"(dst), "l"(src), "r"(sz));
}
#define CP_COMMIT() asm volatile("cp.async.commit_group;")
#define CP_WAIT(N)  asm volatile("cp.async.wait_group %0;" :: "n"(N))

constexpr int STU = 20;          // u32 per smem row (40 halves) -> conflict-free

// ---------------------------------------------------------------------------
// fp16 GEMM: C[M,256] = A[M,K] @ B^T, A,B fp16 (B [256,K] k-major).
// EPI 0: sigmoid(acc+extra[col]) -> f32 | 1: plain -> f32 | 2: APPNP -> f16
// 256 thr, CTA 128x128, warp 64x32, ktile 32 (16 halves * 2), 3-stage cp.async.
// ---------------------------------------------------------------------------
template <int EPI>
__global__ void __launch_bounds__(256, 2)
tc_gemm(const __half* __restrict__ A, long strideA,
        const __half* __restrict__ Bm, long strideB,
        const float* __restrict__ extra, long strideE,
        void* __restrict__ Cv, long strideC,
        int M, int K, int S)
{
    extern __shared__ char smraw[];
    const int t = threadIdx.x;
    const int m0 = blockIdx.x * 128;
    const int col0 = blockIdx.y * 128;
    A += (size_t)blockIdx.z * strideA;
    Bm += (size_t)blockIdx.z * strideB;
    extra += (size_t)blockIdx.z * strideE;

    const int w = t >> 5, lane = t & 31;
    const int g = lane >> 2, tg = lane & 3;
    const int warpM = (w & 1) * 64;
    const int warpN = (w >> 1) * 32;

    constexpr int STAGE_B = 2 * 128 * STU * 4;     // 20480 bytes
    const uint32_t smb = (uint32_t)__cvta_generic_to_shared(smraw);

    float acc[4][4][4];
    #pragma unroll
    for (int i = 0; i < 4; i++)
        #pragma unroll
        for (int j = 0; j < 4; j++)
            #pragma unroll
            for (int q = 0; q < 4; q++) acc[i][j][q] = 0.0f;

    auto stage = [&](int s, int p) {
        const int k0 = s * 32;
        const uint32_t As = smb + p * STAGE_B;
        const uint32_t Bs = As + 128 * STU * 4;
        #pragma unroll
        for (int i = 0; i < 2; i++) {
            int idx = t + i * 256;
            int row = idx >> 2, q = idx & 3;
            int gr = m0 + row, k = k0 + q * 8;
            int sz = (gr < M && k + 8 <= K) ? 16 : 0;
            const void* src = sz ? (const void*)(A + (size_t)gr * K + k) : (const void*)A;
            cp16(As + (row * STU + q * 4) * 4, src, sz);
        }
        #pragma unroll
        for (int i = 0; i < 2; i++) {
            int idx = t + i * 256;
            int row = idx >> 2, q = idx & 3;
            int k = k0 + q * 8;
            int sz = (k + 8 <= K) ? 16 : 0;
            const void* src = sz ? (const void*)(Bm + (size_t)(col0 + row) * K + k)
                                 : (const void*)Bm;
            cp16(Bs + (row * STU + q * 4) * 4, src, sz);
        }
        CP_COMMIT();
    };

    auto compute = [&](int p) {
        const uint32_t* As = (const uint32_t*)(smraw + p * STAGE_B);
        const uint32_t* Bs = As + 128 * STU;
        #pragma unroll
        for (int ks = 0; ks < 2; ks++) {
            const int kb = ks * 8;
            uint32_t af[4][4];
            #pragma unroll
            for (int mt = 0; mt < 4; mt++) {
                const int r = warpM + mt * 16;
                af[mt][0] = As[(r + g) * STU + kb + tg];
                af[mt][1] = As[(r + g + 8) * STU + kb + tg];
                af[mt][2] = As[(r + g) * STU + kb + tg + 4];
                af[mt][3] = As[(r + g + 8) * STU + kb + tg + 4];
            }
            #pragma unroll
            for (int nt = 0; nt < 4; nt++) {
                const int c = warpN + nt * 8 + g;
                uint32_t b0 = Bs[c * STU + kb + tg];
                uint32_t b1 = Bs[c * STU + kb + tg + 4];
                #pragma unroll
                for (int mt = 0; mt < 4; mt++)
                    mma_f16(acc[mt][nt], af[mt], b0, b1);
            }
        }
    };

    stage(0, 0);
    if (S > 1) stage(1, 1);
    for (int s = 0; s < S; s++) {
        const int p = s % 3;
        if (s + 2 < S) { stage(s + 2, (s + 2) % 3); CP_WAIT(2); }
        else if (s + 1 < S) { CP_WAIT(1); }
        else { CP_WAIT(0); }
        __syncthreads();
        compute(p);
        __syncthreads();
    }

    #pragma unroll
    for (int mt = 0; mt < 4; mt++) {
        #pragma unroll
        for (int half = 0; half < 2; half++) {
            int r = m0 + warpM + mt * 16 + g + half * 8;
            if (r >= M) continue;
            #pragma unroll
            for (int nt = 0; nt < 4; nt++) {
                int cc = col0 + warpN + nt * 8 + tg * 2;
                float v0 = acc[mt][nt][half * 2 + 0];
                float v1 = acc[mt][nt][half * 2 + 1];
                if (EPI == 0) {
                    float2 bb = *(const float2*)(extra + cc);
                    float2 o;
                    o.x = 1.0f / (1.0f + __expf(-(v0 + bb.x)));
                    o.y = 1.0f / (1.0f + __expf(-(v1 + bb.y)));
                    *(float2*)((float*)Cv + (size_t)blockIdx.z * strideC
                               + (size_t)r * 256 + cc) = o;
                } else if (EPI == 2) {
                    float2 e = *(const float2*)(extra + (size_t)r * 256 + cc);
                    float o0 = (1.0f - ALPHA_C) * v0 + ALPHA_C * e.x;
                    float o1 = (1.0f - ALPHA_C) * v1 + ALPHA_C * e.y;
                    *(__half2*)((__half*)Cv + (size_t)blockIdx.z * strideC
                                + (size_t)r * 256 + cc) = __floats2half2_rn(o0, o1);
                } else {
                    *(float2*)((float*)Cv + (size_t)blockIdx.z * strideC
                               + (size_t)r * 256 + cc) = make_float2(v0, v1);
                }
            }
        }
    }
}
constexpr unsigned SMEM_TC = 3u * 2u * 128u * STU * 4u;    // 61440 B

// ---------------------------------------------------------------------------
// AV GEMM (fp16): C[392x64] = E[392x392] @ xpHT^T per (b,h);
// epilogue scales rows by isum, adds bias, ELU. CTA 128x64, 8 warps 32x32.
// ---------------------------------------------------------------------------
__global__ void __launch_bounds__(256, 2)
tc_av(const __half* __restrict__ E, const __half* __restrict__ xpHT,
      const float* __restrict__ isum, const float* __restrict__ bias,
      float* __restrict__ out)
{
    extern __shared__ char smraw[];
    const int t = threadIdx.x;
    const int m0 = blockIdx.x * 128;
    const int bh = blockIdx.z;
    const int b = bh >> 2, h = bh & 3;

    const int w = t >> 5, lane = t & 31;
    const int g = lane >> 2, tg = lane & 3;
    const int warpM = (w & 3) * 32;
    const int warpN = (w >> 2) * 32;

    constexpr int STAGE_B = (128 + 64) * STU * 4;   // 15360 bytes
    const uint32_t smb = (uint32_t)__cvta_generic_to_shared(smraw);

    float acc[2][4][4];
    #pragma unroll
    for (int i = 0; i < 2; i++)
        #pragma unroll
        for (int j = 0; j < 4; j++)
            #pragma unroll
            for (int q = 0; q < 4; q++) acc[i][j][q] = 0.0f;

    const __half* Eb = E + (size_t)bh * Nn * Nn;
    const __half* Xb = xpHT + (size_t)bh * 64 * Nn;

    auto stage = [&](int s, int p) {
        const int k0 = s * 32;
        const uint32_t As = smb + p * STAGE_B;
        const uint32_t Bs = As + 128 * STU * 4;
        #pragma unroll
        for (int i = 0; i < 2; i++) {
            int idx = t + i * 256;
            int row = idx >> 2, q = idx & 3;
            int gr = m0 + row, k = k0 + q * 8;
            int sz = (gr < Nn && k + 8 <= Nn) ? 16 : 0;
            const void* src = sz ? (const void*)(Eb + (size_t)gr * Nn + k) : (const void*)Eb;
            cp16(As + (row * STU + q * 4) * 4, src, sz);
        }
        {
            int row = t >> 2, q = t & 3;
            int k = k0 + q * 8;
            int sz = (k + 8 <= Nn) ? 16 : 0;
            const void* src = sz ? (const void*)(Xb + (size_t)row * Nn + k) : (const void*)Xb;
            cp16(Bs + (row * STU + q * 4) * 4, src, sz);
        }
        CP_COMMIT();
    };

    auto compute = [&](int p) {
        const uint32_t* As = (const uint32_t*)(smraw + p * STAGE_B);
        const uint32_t* Bs = As + 128 * STU;
        #pragma unroll
        for (int ks = 0; ks < 2; ks++) {
            const int kb = ks * 8;
            uint32_t af[2][4];
            #pragma unroll
            for (int mt = 0; mt < 2; mt++) {
                const int r = warpM + mt * 16;
                af[mt][0] = As[(r + g) * STU + kb + tg];
                af[mt][1] = As[(r + g + 8) * STU + kb + tg];
                af[mt][2] = As[(r + g) * STU + kb + tg + 4];
                af[mt][3] = As[(r + g + 8) * STU + kb + tg + 4];
            }
            #pragma unroll
            for (int nt = 0; nt < 4; nt++) {
                const int c = warpN + nt * 8 + g;
                uint32_t b0 = Bs[c * STU + kb + tg];
                uint32_t b1 = Bs[c * STU + kb + tg + 4];
                #pragma unroll
                for (int mt = 0; mt < 2; mt++)
                    mma_f16(acc[mt][nt], af[mt], b0, b1);
            }
        }
    };

    constexpr int S = (Nn + 31) / 32;    // 13
    stage(0, 0);
    stage(1, 1);
    for (int s = 0; s < S; s++) {
        const int p = s % 3;
        if (s + 2 < S) { stage(s + 2, (s + 2) % 3); CP_WAIT(2); }
        else if (s + 1 < S) { CP_WAIT(1); }
        else { CP_WAIT(0); }
        __syncthreads();
        compute(p);
        __syncthreads();
    }

    #pragma unroll
    for (int mt = 0; mt < 2; mt++) {
        #pragma unroll
        for (int half = 0; half < 2; half++) {
            int r = m0 + warpM + mt * 16 + g + half * 8;
            if (r >= Nn) continue;
            float sc = isum[bh * Nn + r];
            #pragma unroll
            for (int nt = 0; nt < 4; nt++) {
                int cc = warpN + nt * 8 + tg * 2;
                float2 bb = *(const float2*)(bias + h * 64 + cc);
                float v0 = acc[mt][nt][half * 2 + 0] * sc + bb.x;
                float v1 = acc[mt][nt][half * 2 + 1] * sc + bb.y;
                v0 = (v0 > 0.0f) ? v0 : expm1f(v0);
                v1 = (v1 > 0.0f) ? v1 : expm1f(v1);
                *(float2*)(out + ((size_t)(b * Nn + r)) * 256 + h * 64 + cc) =
                    make_float2(v0, v1);
            }
        }
    }
}
constexpr unsigned SMEM_AV = 3u * (128u + 64u) * STU * 4u;  // 46080 B

// ---------------------------------------------------------------------------
// Elementwise fp32 -> fp16 (vectorized x4)
// ---------------------------------------------------------------------------
__global__ void k_f2h(const float* __restrict__ in, __half* __restrict__ out,
                      size_t n4)
{
    size_t i = (size_t)blockIdx.x * blockDim.x + threadIdx.x;
    if (i >= n4) return;
    float4 v = *(const float4*)(in + i * 4);
    __half2 p0 = __floats2half2_rn(v.x, v.y);
    __half2 p1 = __floats2half2_rn(v.z, v.w);
    *(__half2*)(out + i * 4) = p0;
    *(__half2*)(out + i * 4 + 2) = p1;
}

// ---------------------------------------------------------------------------
// Tiled transpose fp32 -> fp16: in [R][C] -> out [C][R], batched via z
// ---------------------------------------------------------------------------
__global__ void k_transpose_h(const float* __restrict__ in, __half* __restrict__ out,
                              int R, int C, long sIn, long sOut)
{
    __shared__ float tile[32][33];
    in += (size_t)blockIdx.z * sIn;
    out += (size_t)blockIdx.z * sOut;
    int c = blockIdx.x * 32 + threadIdx.x;
    int r = blockIdx.y * 32 + threadIdx.y;
    #pragma unroll
    for (int i = 0; i < 4; i++) {
        int rr = r + i * 8;
        if (rr < R && c < C) tile[threadIdx.y + i * 8][threadIdx.x] = in[(size_t)rr * C + c];
    }
    __syncthreads();
    int c2 = blockIdx.y * 32 + threadIdx.x;
    int r2 = blockIdx.x * 32 + threadIdx.y;
    #pragma unroll
    for (int i = 0; i < 4; i++) {
        int rr = r2 + i * 8;
        if (rr < C && c2 < R)
            out[(size_t)rr * R + c2] = __float2half_rn(tile[threadIdx.x][threadIdx.y + i * 8]);
    }
}

// ---------------------------------------------------------------------------
// xp [b,n,256] fp32 -> xpHT [(b,h), o, n] fp16
// ---------------------------------------------------------------------------
__global__ void k_xpT(const float* __restrict__ xp, __half* __restrict__ xpHT)
{
    __shared__ float tile[32][33];
    const int bh = blockIdx.z;
    const int b = bh >> 2, h = bh & 3;
    int o = blockIdx.y * 32 + threadIdx.x;
    int n = blockIdx.x * 32 + threadIdx.y;
    #pragma unroll
    for (int i = 0; i < 4; i++) {
        int nn = n + i * 8;
        if (nn < Nn)
            tile[threadIdx.y + i * 8][threadIdx.x] =
                xp[((size_t)(b * Nn + nn)) * 256 + h * 64 + o];
    }
    __syncthreads();
    int n2 = blockIdx.x * 32 + threadIdx.x;
    int o2 = blockIdx.y * 32 + threadIdx.y;
    #pragma unroll
    for (int i = 0; i < 4; i++) {
        int oo = o2 + i * 8;
        if (n2 < Nn)
            xpHT[((size_t)bh * 64 + oo) * Nn + n2] =
                __float2half_rn(tile[threadIdx.x][threadIdx.y + i * 8]);
    }
}

// ---------------------------------------------------------------------------
// Mask bitmap
// ---------------------------------------------------------------------------
__global__ void k_mask(const float* __restrict__ a, unsigned* __restrict__ mb)
{
    int i = blockIdx.x * blockDim.x + threadIdx.x;
    if (i >= Nn * 13) return;
    int n = i / 13, w = i - n * 13;
    unsigned bits = 0;
    #pragma unroll
    for (int j = 0; j < 32; j++) {
        int m = w * 32 + j;
        if (m < Nn && m != n && a[(size_t)n * Nn + m] == 0.0f) bits |= 1u << j;
    }
    mb[i] = bits;
}

// ---------------------------------------------------------------------------
// s/ng projections (one warp per (b,n))
// ---------------------------------------------------------------------------
__global__ void k_proj(const float* __restrict__ xp,
                       const float* __restrict__ ak_self,
                       const float* __restrict__ ak_neigh,
                       float* __restrict__ sT, float* __restrict__ ngT)
{
    int gw = (blockIdx.x * blockDim.x + threadIdx.x) >> 5;
    int lane = threadIdx.x & 31;
    if (gw >= BN) return;
    int b = gw / Nn, n = gw - b * Nn;
    const float* xr = xp + (size_t)gw * HO;
    #pragma unroll
    for (int h = 0; h < Hh; h++) {
        float v0 = xr[h * 64 + lane];
        float v1 = xr[h * 64 + 32 + lane];
        float ss = v0 * ak_self[lane * Hh + h] + v1 * ak_self[(lane + 32) * Hh + h];
        float ng = v0 * ak_neigh[lane * Hh + h] + v1 * ak_neigh[(lane + 32) * Hh + h];
        #pragma unroll
        for (int off = 16; off > 0; off >>= 1) {
            ss += __shfl_down_sync(0xffffffffu, ss, off);
            ng += __shfl_down_sync(0xffffffffu, ng, off);
        }
        if (lane == 0) {
            sT[(b * Hh + h) * Nn + n] = ss;
            ngT[(b * Hh + h) * Nn + n] = ng;
        }
    }
}

// ---------------------------------------------------------------------------
// Stats + E write: per (b,h,n) row: rowmax, E=exp(l-m) fp16, isum.
// ---------------------------------------------------------------------------
__global__ void k_stats_e(const unsigned* __restrict__ mb,
                          const float* __restrict__ sT,
                          const float* __restrict__ ngT,
                          __half* __restrict__ E,
                          float* __restrict__ isum)
{
    const int n = blockIdx.x, b = blockIdx.y;
    const int h = threadIdx.x >> 5, lane = threadIdx.x & 31;
    const int bh = b * Hh + h;
    const float sv = sT[bh * Nn + n];
    const float* ngr = ngT + (size_t)bh * Nn;
    __half* Erow = E + ((size_t)bh * Nn + n) * Nn;

    float lv[13];
    float m = -3.0e38f;
    #pragma unroll
    for (int it = 0; it < 13; it++) {
        int mm = lane + it * 32;
        unsigned wd = mb[n * 13 + it];
        float l = -3.0e38f;
        if (mm < Nn && !((wd >> lane) & 1u)) {
            float l0 = sv + ngr[mm];
            l = (l0 > 0.0f) ? l0 : LEAKY_C * l0;
        }
        lv[it] = l;
        m = fmaxf(m, l);
    }
    #pragma unroll
    for (int off = 16; off > 0; off >>= 1)
        m = fmaxf(m, __shfl_xor_sync(0xffffffffu, m, off));

    float s = 0.0f;
    #pragma unroll
    for (int it = 0; it < 13; it++) {
        int mm = lane + it * 32;
        float e = 0.0f;
        if (lv[it] > -1.0e38f) e = __expf(lv[it] - m);
        s += e;
        if (mm < Nn) Erow[mm] = __float2half_rn(e);
    }
    #pragma unroll
    for (int off = 16; off > 0; off >>= 1)
        s += __shfl_xor_sync(0xffffffffu, s, off);

    if (lane == 0) isum[bh * Nn + n] = 1.0f / s;
}

// ---------------------------------------------------------------------------
extern "C" void kernel_launch(void* const* d_in, const int* in_sizes, int n_in,
                              void* d_out, int out_size)
{
    const float* x        = (const float*)d_in[0];
    const float* a        = (const float*)d_in[1];
    const float* w_mlp    = (const float*)d_in[2];
    const float* b_mlp    = (const float*)d_in[3];
    const float* kern     = (const float*)d_in[4];
    const float* ak_self  = (const float*)d_in[5];
    const float* ak_neigh = (const float*)d_in[6];
    const float* bias     = (const float*)d_in[7];
    float* out = (float*)d_out;

    __half *p_xH, *p_wTh, *p_kTh, *p_aH, *p_mlpTh, *p_zH, *p_E, *p_xpHT;
    float *p_mlp, *p_xp, *p_sT, *p_ngT, *p_isum;
    unsigned* p_mbits;
    cudaGetSymbolAddress((void**)&p_xH, g_xH);
    cudaGetSymbolAddress((void**)&p_wTh, g_wTh);
    cudaGetSymbolAddress((void**)&p_kTh, g_kTh);
    cudaGetSymbolAddress((void**)&p_aH, g_aH);
    cudaGetSymbolAddress((void**)&p_mlp, g_mlp);
    cudaGetSymbolAddress((void**)&p_mlpTh, g_mlpTh);
    cudaGetSymbolAddress((void**)&p_zH, g_zH);
    cudaGetSymbolAddress((void**)&p_xp, g_xp);
    cudaGetSymbolAddress((void**)&p_sT, g_sT);
    cudaGetSymbolAddress((void**)&p_ngT, g_ngT);
    cudaGetSymbolAddress((void**)&p_isum, g_isum);
    cudaGetSymbolAddress((void**)&p_mbits, g_mbits);
    cudaGetSymbolAddress((void**)&p_E, g_E);
    cudaGetSymbolAddress((void**)&p_xpHT, g_xpHT);

    cudaFuncSetAttribute(tc_gemm<0>, cudaFuncAttributeMaxDynamicSharedMemorySize, SMEM_TC);
    cudaFuncSetAttribute(tc_gemm<1>, cudaFuncAttributeMaxDynamicSharedMemorySize, SMEM_TC);
    cudaFuncSetAttribute(tc_gemm<2>, cudaFuncAttributeMaxDynamicSharedMemorySize, SMEM_TC);
    cudaFuncSetAttribute(tc_av, cudaFuncAttributeMaxDynamicSharedMemorySize, SMEM_AV);

    // conversions + mask
    k_f2h<<<((size_t)BN * HO / 4 + 255) / 256, 256>>>(x, p_xH, (size_t)BN * HO / 4);
    k_f2h<<<(Nn * Nn / 4 + 255) / 256, 256>>>(a, p_aH, Nn * Nn / 4);
    k_transpose_h<<<dim3(8, 8, 1), dim3(32, 8)>>>(w_mlp, p_wTh, 256, 256, 0, 0);
    k_transpose_h<<<dim3(8, 8, 1), dim3(32, 8)>>>(kern, p_kTh, 256, 256, 0, 0);
    k_mask<<<(Nn * 13 + 127) / 128, 128>>>(a, p_mbits);

    // 1. mlp = sigmoid(x @ w_mlp + b)   -> fp32
    tc_gemm<0><<<dim3((BN + 127) / 128, 2, 1), 256, SMEM_TC>>>(
        p_xH, 0, p_wTh, 0, b_mlp, 0, p_mlp, 0, BN, 256, 8);
    // 2. mlpT per batch -> fp16
    k_transpose_h<<<dim3(8, 13, Bb), dim3(32, 8)>>>(p_mlp, p_mlpTh, Nn, 256,
                                                    (long)Nn * 256, (long)Nn * 256);
    // 3. z = 0.8*a@mlp + 0.2*mlp        -> fp16
    tc_gemm<2><<<dim3(4, 2, Bb), 256, SMEM_TC>>>(
        p_aH, 0, p_mlpTh, (long)Nn * 256, p_mlp, (long)Nn * 256,
        p_zH, (long)Nn * 256, Nn, Nn, 13);
    // 4. xp = z @ kernel                -> fp32
    tc_gemm<1><<<dim3((BN + 127) / 128, 2, 1), 256, SMEM_TC>>>(
        p_zH, 0, p_kTh, 0, nullptr, 0, p_xp, 0, BN, 256, 8);
    // 5. s / ng projections
    k_proj<<<(BN * 32 + 255) / 256, 256>>>(p_xp, ak_self, ak_neigh, p_sT, p_ngT);
    // 6. xp -> fp16 transposed per (b,h)
    k_xpT<<<dim3(13, 2, BH), dim3(32, 8)>>>(p_xp, p_xpHT);
    // 7. stats + E (fp16)
    k_stats_e<<<dim3(Nn, Bb), 128>>>(p_mbits, p_sT, p_ngT, p_E, p_isum);
    // 8. AV gemm + scale + bias + ELU
    tc_av<<<dim3((Nn + 127) / 128, 1, BH), 256, SMEM_AV>>>(
        p_E, p_xpHT, p_isum, bias, out);
}